// round 1
// baseline (speedup 1.0000x reference)
#include <cuda_runtime.h>
#include <cstdint>

// ---------------------------------------------------------------------------
// GCN: 4x GCNConv(128->128) + output linear(128->128), N=100000, E=1600000.
// Scratch lives in __device__ globals (no allocation allowed).
// ---------------------------------------------------------------------------

#define NMAX 100096
#define FDIM 128

__device__ float g_t[(size_t)NMAX * FDIM];    // post-GEMM h = act(x) @ W
__device__ float g_h[(size_t)NMAX * FDIM];    // aggregated output (next input)
__device__ float g_deg[NMAX];
__device__ float g_dinv[NMAX];

// ---------------- degree / normalization ----------------

__global__ void k_deg_init(float* __restrict__ deg, int n) {
    int i = blockIdx.x * blockDim.x + threadIdx.x;
    if (i < n) deg[i] = 1.0f;  // self-loop weight
}

__global__ void k_deg_edge(const int* __restrict__ col, const float* __restrict__ ew,
                           float* __restrict__ deg, int E) {
    int e = blockIdx.x * blockDim.x + threadIdx.x;
    if (e < E) atomicAdd(&deg[col[e]], ew[e]);
}

__global__ void k_dinv(const float* __restrict__ deg, float* __restrict__ dinv, int n) {
    int i = blockIdx.x * blockDim.x + threadIdx.x;
    if (i < n) {
        float d = deg[i];
        dinv[i] = (d > 0.0f) ? rsqrtf(d) : 0.0f;
    }
}

// ---------------- fp32 SGEMM: C[M,128] = act(A[M,128]) @ W[128,128] (+bias) ----------------
// BM=128, BN=128, BK=8, 256 threads, 8x8 per-thread micro-tile.

__global__ void __launch_bounds__(256) k_gemm(
    const float* __restrict__ A, const float* __restrict__ W,
    const float* __restrict__ bias, float* __restrict__ C,
    int M, int doRelu, int doBias)
{
    __shared__ float As[8][132];   // [k][row], padded for conflict-free stores/float4 reads
    __shared__ float Bs[8][128];   // [k][col]

    const int tid = threadIdx.x;
    const int rbase = blockIdx.x * 128;
    const int tr = tid >> 4;      // 0..15 -> row group
    const int tc = tid & 15;      // 0..15 -> col group

    const int arow = tid >> 1;          // 0..127
    const int ac4  = (tid & 1) * 4;     // 0 or 4
    const int brow = tid >> 5;          // 0..7
    const int bc4  = (tid & 31) * 4;    // 0..124
    const int grow = rbase + arow;

    float acc[8][8];
#pragma unroll
    for (int m = 0; m < 8; m++)
#pragma unroll
        for (int n = 0; n < 8; n++) acc[m][n] = 0.0f;

    for (int k0 = 0; k0 < 128; k0 += 8) {
        float4 av = make_float4(0.f, 0.f, 0.f, 0.f);
        if (grow < M)
            av = *reinterpret_cast<const float4*>(A + (size_t)grow * FDIM + k0 + ac4);
        if (doRelu) {
            av.x = fmaxf(av.x, 0.f); av.y = fmaxf(av.y, 0.f);
            av.z = fmaxf(av.z, 0.f); av.w = fmaxf(av.w, 0.f);
        }
        As[ac4 + 0][arow] = av.x;
        As[ac4 + 1][arow] = av.y;
        As[ac4 + 2][arow] = av.z;
        As[ac4 + 3][arow] = av.w;

        float4 bv = *reinterpret_cast<const float4*>(W + (size_t)(k0 + brow) * FDIM + bc4);
        *reinterpret_cast<float4*>(&Bs[brow][bc4]) = bv;

        __syncthreads();

#pragma unroll
        for (int kk = 0; kk < 8; kk++) {
            float a[8], b[8];
            float4 a0 = *reinterpret_cast<const float4*>(&As[kk][tr * 8]);
            float4 a1 = *reinterpret_cast<const float4*>(&As[kk][tr * 8 + 4]);
            float4 b0 = *reinterpret_cast<const float4*>(&Bs[kk][tc * 8]);
            float4 b1 = *reinterpret_cast<const float4*>(&Bs[kk][tc * 8 + 4]);
            a[0]=a0.x; a[1]=a0.y; a[2]=a0.z; a[3]=a0.w;
            a[4]=a1.x; a[5]=a1.y; a[6]=a1.z; a[7]=a1.w;
            b[0]=b0.x; b[1]=b0.y; b[2]=b0.z; b[3]=b0.w;
            b[4]=b1.x; b[5]=b1.y; b[6]=b1.z; b[7]=b1.w;
#pragma unroll
            for (int m = 0; m < 8; m++)
#pragma unroll
                for (int n = 0; n < 8; n++)
                    acc[m][n] = fmaf(a[m], b[n], acc[m][n]);
        }
        __syncthreads();
    }

    float bv0[8];
    if (doBias) {
#pragma unroll
        for (int n = 0; n < 8; n++) bv0[n] = bias[tc * 8 + n];
    } else {
#pragma unroll
        for (int n = 0; n < 8; n++) bv0[n] = 0.0f;
    }

#pragma unroll
    for (int m = 0; m < 8; m++) {
        int row = rbase + tr * 8 + m;
        if (row < M) {
            float4 o0, o1;
            o0.x = acc[m][0] + bv0[0]; o0.y = acc[m][1] + bv0[1];
            o0.z = acc[m][2] + bv0[2]; o0.w = acc[m][3] + bv0[3];
            o1.x = acc[m][4] + bv0[4]; o1.y = acc[m][5] + bv0[5];
            o1.z = acc[m][6] + bv0[6]; o1.w = acc[m][7] + bv0[7];
            float* cp = C + (size_t)row * FDIM + tc * 8;
            *reinterpret_cast<float4*>(cp)     = o0;
            *reinterpret_cast<float4*>(cp + 4) = o1;
        }
    }
}

// ---------------- self-loop init: h = t * dinv^2 + bias ----------------

__global__ void k_selfinit(const float* __restrict__ t, const float* __restrict__ dinv,
                           const float* __restrict__ bias, float* __restrict__ h, int n) {
    int i = blockIdx.x * blockDim.x + threadIdx.x;   // float4 index
    int total = n * (FDIM / 4);
    if (i >= total) return;
    int node = i >> 5;             // 32 float4 per node
    int f4   = (i & 31) * 4;
    float d = dinv[node];
    float d2 = d * d;
    float4 tv = *reinterpret_cast<const float4*>(t + (size_t)node * FDIM + f4);
    float4 bv = *reinterpret_cast<const float4*>(bias + f4);
    float4 o;
    o.x = fmaf(tv.x, d2, bv.x);
    o.y = fmaf(tv.y, d2, bv.y);
    o.z = fmaf(tv.z, d2, bv.z);
    o.w = fmaf(tv.w, d2, bv.w);
    *reinterpret_cast<float4*>(h + (size_t)node * FDIM + f4) = o;
}

// ---------------- edge scatter: h[col] += norm * t[row], one warp per edge ----------------

__global__ void __launch_bounds__(256) k_scatter(
    const int* __restrict__ row, const int* __restrict__ col,
    const float* __restrict__ ew, const float* __restrict__ dinv,
    const float* __restrict__ t, float* __restrict__ h, int E)
{
    int e = blockIdx.x * 8 + (threadIdx.x >> 5);
    if (e >= E) return;
    int lane = threadIdx.x & 31;
    int r = __ldg(row + e);
    int c = __ldg(col + e);
    float norm = __ldg(dinv + r) * __ldg(ew + e) * __ldg(dinv + c);
    float4 v = *reinterpret_cast<const float4*>(t + (size_t)r * FDIM + lane * 4);
    float* dst = h + (size_t)c * FDIM + lane * 4;
    asm volatile(
        "red.global.add.v4.f32 [%0], {%1, %2, %3, %4};"
        :: "l"(dst), "f"(v.x * norm), "f"(v.y * norm), "f"(v.z * norm), "f"(v.w * norm)
        : "memory");
}

// ---------------- launch ----------------

extern "C" void kernel_launch(void* const* d_in, const int* in_sizes, int n_in,
                              void* d_out, int out_size) {
    const float* x    = (const float*)d_in[0];
    const int*   ei   = (const int*)  d_in[1];
    const float* ew   = (const float*)d_in[2];
    const float* Wc[4] = {(const float*)d_in[3], (const float*)d_in[5],
                          (const float*)d_in[7], (const float*)d_in[9]};
    const float* bc[4] = {(const float*)d_in[4], (const float*)d_in[6],
                          (const float*)d_in[8], (const float*)d_in[10]};
    const float* Wout = (const float*)d_in[11];
    const float* bout = (const float*)d_in[12];
    float* out = (float*)d_out;

    const int N = in_sizes[0] / FDIM;
    const int E = in_sizes[2];
    const int* rowp = ei;
    const int* colp = ei + E;

    float *t, *h, *deg, *dinv;
    cudaGetSymbolAddress((void**)&t, g_t);
    cudaGetSymbolAddress((void**)&h, g_h);
    cudaGetSymbolAddress((void**)&deg, g_deg);
    cudaGetSymbolAddress((void**)&dinv, g_dinv);

    const int TB = 256;
    // degree + normalization
    k_deg_init<<<(N + TB - 1) / TB, TB>>>(deg, N);
    k_deg_edge<<<(E + TB - 1) / TB, TB>>>(colp, ew, deg, E);
    k_dinv<<<(N + TB - 1) / TB, TB>>>(deg, dinv, N);

    const int gemmBlocks = (N + 127) / 128;
    const int initBlocks = (N * (FDIM / 4) + TB - 1) / TB;
    const int scatBlocks = (E + 7) / 8;

    // 4 GCNConv layers: relu fused into the A-load of layers 1..3's GEMM
    for (int l = 0; l < 4; l++) {
        const float* src = (l == 0) ? x : h;
        int relu = (l == 0) ? 0 : 1;
        k_gemm<<<gemmBlocks, TB>>>(src, Wc[l], nullptr, t, N, relu, 0);
        k_selfinit<<<initBlocks, TB>>>(t, dinv, bc[l], h, N);
        k_scatter<<<scatBlocks, TB>>>(rowp, colp, ew, dinv, t, h, E);
    }

    // output projection (no relu on conv-4 output)
    k_gemm<<<gemmBlocks, TB>>>(h, Wout, bout, out, N, 0, 1);
}

// round 2
// speedup vs baseline: 1.5769x; 1.5769x over previous
#include <cuda_runtime.h>
#include <cstdint>

// ---------------------------------------------------------------------------
// GCN: 4x GCNConv(128->128) + output linear(128->128), N=100000, E=1600000.
// Round 2: CSR-by-destination gather (no float atomics), selfinit fused.
// ---------------------------------------------------------------------------

#define NMAX 100096
#define EMAX 1600000
#define FDIM 128

__device__ float g_t[(size_t)NMAX * FDIM];    // post-GEMM h = act(x) @ W
__device__ float g_h[(size_t)NMAX * FDIM];    // aggregated output (next input)
__device__ float g_deg[NMAX];
__device__ float g_dinv[NMAX];
__device__ int   g_cnt[NMAX];                 // in-degree histogram
__device__ int   g_rowptr[NMAX + 1];          // CSR offsets
__device__ int   g_cursor[NMAX];              // fill cursors
__device__ int   g_srow[EMAX];                // sorted source node per edge
__device__ float g_snorm[EMAX];               // sorted norm per edge

// ---------------- degree + histogram ----------------

__global__ void k_init(float* __restrict__ deg, int* __restrict__ cnt,
                       int* __restrict__ cur, int n) {
    int i = blockIdx.x * blockDim.x + threadIdx.x;
    if (i < n) { deg[i] = 1.0f; cnt[i] = 0; cur[i] = 0; }
}

__global__ void k_deg_hist(const int* __restrict__ col, const float* __restrict__ ew,
                           float* __restrict__ deg, int* __restrict__ cnt, int E) {
    int e = blockIdx.x * blockDim.x + threadIdx.x;
    if (e < E) {
        int c = col[e];
        atomicAdd(&deg[c], ew[e]);
        atomicAdd(&cnt[c], 1);
    }
}

__global__ void k_dinv(const float* __restrict__ deg, float* __restrict__ dinv, int n) {
    int i = blockIdx.x * blockDim.x + threadIdx.x;
    if (i < n) {
        float d = deg[i];
        dinv[i] = (d > 0.0f) ? rsqrtf(d) : 0.0f;
    }
}

// ---------------- single-block exclusive scan over cnt -> rowptr ----------------

__global__ void __launch_bounds__(1024) k_scan(const int* __restrict__ cnt,
                                               int* __restrict__ rowptr, int n) {
    __shared__ int sums[1024];
    const int tid = threadIdx.x;
    const int chunk = (n + 1023) / 1024;
    const int lo = tid * chunk;
    const int hi = min(lo + chunk, n);

    int s = 0;
    for (int i = lo; i < hi; i++) s += cnt[i];
    sums[tid] = s;
    __syncthreads();

    // Hillis-Steele inclusive scan on sums
    for (int ofs = 1; ofs < 1024; ofs <<= 1) {
        int v = (tid >= ofs) ? sums[tid - ofs] : 0;
        __syncthreads();
        sums[tid] += v;
        __syncthreads();
    }

    int run = (tid == 0) ? 0 : sums[tid - 1];   // exclusive base for this chunk
    for (int i = lo; i < hi; i++) {
        rowptr[i] = run;
        run += cnt[i];
    }
    if (tid == 1023) rowptr[n] = run;
}

// ---------------- counting-sort fill: sorted (row, norm) per destination ----------------

__global__ void k_fill(const int* __restrict__ row, const int* __restrict__ col,
                       const float* __restrict__ ew, const float* __restrict__ dinv,
                       const int* __restrict__ rowptr, int* __restrict__ cur,
                       int* __restrict__ srow, float* __restrict__ snorm, int E) {
    int e = blockIdx.x * blockDim.x + threadIdx.x;
    if (e >= E) return;
    int r = row[e];
    int c = col[e];
    int pos = rowptr[c] + atomicAdd(&cur[c], 1);
    srow[pos] = r;
    snorm[pos] = dinv[r] * ew[e] * dinv[c];
}

// ---------------- fp32 SGEMM: C[M,128] = act(A[M,128]) @ W[128,128] (+bias) ----------------

__global__ void __launch_bounds__(256) k_gemm(
    const float* __restrict__ A, const float* __restrict__ W,
    const float* __restrict__ bias, float* __restrict__ C,
    int M, int doRelu, int doBias)
{
    __shared__ float As[8][132];
    __shared__ float Bs[8][128];

    const int tid = threadIdx.x;
    const int rbase = blockIdx.x * 128;
    const int tr = tid >> 4;
    const int tc = tid & 15;

    const int arow = tid >> 1;
    const int ac4  = (tid & 1) * 4;
    const int brow = tid >> 5;
    const int bc4  = (tid & 31) * 4;
    const int grow = rbase + arow;

    float acc[8][8];
#pragma unroll
    for (int m = 0; m < 8; m++)
#pragma unroll
        for (int n = 0; n < 8; n++) acc[m][n] = 0.0f;

    for (int k0 = 0; k0 < 128; k0 += 8) {
        float4 av = make_float4(0.f, 0.f, 0.f, 0.f);
        if (grow < M)
            av = *reinterpret_cast<const float4*>(A + (size_t)grow * FDIM + k0 + ac4);
        if (doRelu) {
            av.x = fmaxf(av.x, 0.f); av.y = fmaxf(av.y, 0.f);
            av.z = fmaxf(av.z, 0.f); av.w = fmaxf(av.w, 0.f);
        }
        As[ac4 + 0][arow] = av.x;
        As[ac4 + 1][arow] = av.y;
        As[ac4 + 2][arow] = av.z;
        As[ac4 + 3][arow] = av.w;

        float4 bv = *reinterpret_cast<const float4*>(W + (size_t)(k0 + brow) * FDIM + bc4);
        *reinterpret_cast<float4*>(&Bs[brow][bc4]) = bv;

        __syncthreads();

#pragma unroll
        for (int kk = 0; kk < 8; kk++) {
            float a[8], b[8];
            float4 a0 = *reinterpret_cast<const float4*>(&As[kk][tr * 8]);
            float4 a1 = *reinterpret_cast<const float4*>(&As[kk][tr * 8 + 4]);
            float4 b0 = *reinterpret_cast<const float4*>(&Bs[kk][tc * 8]);
            float4 b1 = *reinterpret_cast<const float4*>(&Bs[kk][tc * 8 + 4]);
            a[0]=a0.x; a[1]=a0.y; a[2]=a0.z; a[3]=a0.w;
            a[4]=a1.x; a[5]=a1.y; a[6]=a1.z; a[7]=a1.w;
            b[0]=b0.x; b[1]=b0.y; b[2]=b0.z; b[3]=b0.w;
            b[4]=b1.x; b[5]=b1.y; b[6]=b1.z; b[7]=b1.w;
#pragma unroll
            for (int m = 0; m < 8; m++)
#pragma unroll
                for (int n = 0; n < 8; n++)
                    acc[m][n] = fmaf(a[m], b[n], acc[m][n]);
        }
        __syncthreads();
    }

    float bv0[8];
    if (doBias) {
#pragma unroll
        for (int n = 0; n < 8; n++) bv0[n] = bias[tc * 8 + n];
    } else {
#pragma unroll
        for (int n = 0; n < 8; n++) bv0[n] = 0.0f;
    }

#pragma unroll
    for (int m = 0; m < 8; m++) {
        int row = rbase + tr * 8 + m;
        if (row < M) {
            float4 o0, o1;
            o0.x = acc[m][0] + bv0[0]; o0.y = acc[m][1] + bv0[1];
            o0.z = acc[m][2] + bv0[2]; o0.w = acc[m][3] + bv0[3];
            o1.x = acc[m][4] + bv0[4]; o1.y = acc[m][5] + bv0[5];
            o1.z = acc[m][6] + bv0[6]; o1.w = acc[m][7] + bv0[7];
            float* cp = C + (size_t)row * FDIM + tc * 8;
            *reinterpret_cast<float4*>(cp)     = o0;
            *reinterpret_cast<float4*>(cp + 4) = o1;
        }
    }
}

// ---------------- CSR aggregate: one warp per node ----------------
// h[node] = t[node]*dinv^2 + bias + sum_j norm_j * t[srow_j]

__global__ void __launch_bounds__(256) k_aggregate(
    const int* __restrict__ rowptr, const int* __restrict__ srow,
    const float* __restrict__ snorm, const float* __restrict__ dinv,
    const float* __restrict__ bias, const float* __restrict__ t,
    float* __restrict__ h, int n)
{
    int node = blockIdx.x * 8 + (threadIdx.x >> 5);
    if (node >= n) return;
    const int lane = threadIdx.x & 31;
    const int f4 = lane * 4;

    float d = __ldg(dinv + node);
    float d2 = d * d;
    float4 tv = *reinterpret_cast<const float4*>(t + (size_t)node * FDIM + f4);
    float4 bv = *reinterpret_cast<const float4*>(bias + f4);
    float4 acc;
    acc.x = fmaf(tv.x, d2, bv.x);
    acc.y = fmaf(tv.y, d2, bv.y);
    acc.z = fmaf(tv.z, d2, bv.z);
    acc.w = fmaf(tv.w, d2, bv.w);

    int j = __ldg(rowptr + node);
    const int jend = __ldg(rowptr + node + 1);

    // unroll by 2 for MLP
    for (; j + 1 < jend; j += 2) {
        int r0 = __ldg(srow + j);
        int r1 = __ldg(srow + j + 1);
        float w0 = __ldg(snorm + j);
        float w1 = __ldg(snorm + j + 1);
        float4 v0 = *reinterpret_cast<const float4*>(t + (size_t)r0 * FDIM + f4);
        float4 v1 = *reinterpret_cast<const float4*>(t + (size_t)r1 * FDIM + f4);
        acc.x = fmaf(v0.x, w0, acc.x); acc.y = fmaf(v0.y, w0, acc.y);
        acc.z = fmaf(v0.z, w0, acc.z); acc.w = fmaf(v0.w, w0, acc.w);
        acc.x = fmaf(v1.x, w1, acc.x); acc.y = fmaf(v1.y, w1, acc.y);
        acc.z = fmaf(v1.z, w1, acc.z); acc.w = fmaf(v1.w, w1, acc.w);
    }
    if (j < jend) {
        int r0 = __ldg(srow + j);
        float w0 = __ldg(snorm + j);
        float4 v0 = *reinterpret_cast<const float4*>(t + (size_t)r0 * FDIM + f4);
        acc.x = fmaf(v0.x, w0, acc.x); acc.y = fmaf(v0.y, w0, acc.y);
        acc.z = fmaf(v0.z, w0, acc.z); acc.w = fmaf(v0.w, w0, acc.w);
    }

    *reinterpret_cast<float4*>(h + (size_t)node * FDIM + f4) = acc;
}

// ---------------- launch ----------------

extern "C" void kernel_launch(void* const* d_in, const int* in_sizes, int n_in,
                              void* d_out, int out_size) {
    const float* x    = (const float*)d_in[0];
    const int*   ei   = (const int*)  d_in[1];
    const float* ew   = (const float*)d_in[2];
    const float* Wc[4] = {(const float*)d_in[3], (const float*)d_in[5],
                          (const float*)d_in[7], (const float*)d_in[9]};
    const float* bc[4] = {(const float*)d_in[4], (const float*)d_in[6],
                          (const float*)d_in[8], (const float*)d_in[10]};
    const float* Wout = (const float*)d_in[11];
    const float* bout = (const float*)d_in[12];
    float* out = (float*)d_out;

    const int N = in_sizes[0] / FDIM;
    const int E = in_sizes[2];
    const int* rowp = ei;
    const int* colp = ei + E;

    float *t, *h, *deg, *dinv, *snorm;
    int *cnt, *rowptr, *cur, *srow;
    cudaGetSymbolAddress((void**)&t, g_t);
    cudaGetSymbolAddress((void**)&h, g_h);
    cudaGetSymbolAddress((void**)&deg, g_deg);
    cudaGetSymbolAddress((void**)&dinv, g_dinv);
    cudaGetSymbolAddress((void**)&cnt, g_cnt);
    cudaGetSymbolAddress((void**)&rowptr, g_rowptr);
    cudaGetSymbolAddress((void**)&cur, g_cursor);
    cudaGetSymbolAddress((void**)&srow, g_srow);
    cudaGetSymbolAddress((void**)&snorm, g_snorm);

    const int TB = 256;

    // one-time CSR build
    k_init<<<(N + TB - 1) / TB, TB>>>(deg, cnt, cur, N);
    k_deg_hist<<<(E + TB - 1) / TB, TB>>>(colp, ew, deg, cnt, E);
    k_dinv<<<(N + TB - 1) / TB, TB>>>(deg, dinv, N);
    k_scan<<<1, 1024>>>(cnt, rowptr, N);
    k_fill<<<(E + TB - 1) / TB, TB>>>(rowp, colp, ew, dinv, rowptr, cur, srow, snorm, E);

    const int gemmBlocks = (N + 127) / 128;
    const int aggBlocks  = (N + 7) / 8;

    for (int l = 0; l < 4; l++) {
        const float* src = (l == 0) ? x : h;
        int relu = (l == 0) ? 0 : 1;
        k_gemm<<<gemmBlocks, TB>>>(src, Wc[l], nullptr, t, N, relu, 0);
        k_aggregate<<<aggBlocks, TB>>>(rowptr, srow, snorm, dinv, bc[l], t, h, N);
    }

    k_gemm<<<gemmBlocks, TB>>>(h, Wout, bout, out, N, 0, 1);
}

// round 3
// speedup vs baseline: 1.7519x; 1.1109x over previous
#include <cuda_runtime.h>
#include <cstdint>

// ---------------------------------------------------------------------------
// GCN: 4x GCNConv(128->128) + output linear(128->128), N=100000, E=1600000.
// Round 3: multi-block scan (k_scan was 94us single-block -> ~8us).
// ---------------------------------------------------------------------------

#define NMAX 100096
#define EMAX 1600000
#define FDIM 128
#define SCAN_B 1024
#define MAXBLK 128   // ceil(NMAX/SCAN_B) = 98 <= 128

__device__ float g_t[(size_t)NMAX * FDIM];
__device__ float g_h[(size_t)NMAX * FDIM];
__device__ float g_deg[NMAX];
__device__ float g_dinv[NMAX];
__device__ int   g_cnt[NMAX];
__device__ int   g_rowptr[NMAX + 1];
__device__ int   g_cursor[NMAX];
__device__ int   g_srow[EMAX];
__device__ float g_snorm[EMAX];
__device__ int   g_bsum[MAXBLK];
__device__ int   g_boffs[MAXBLK];

// ---------------- degree + histogram ----------------

__global__ void k_init(float* __restrict__ deg, int* __restrict__ cnt,
                       int* __restrict__ cur, int n) {
    int i = blockIdx.x * blockDim.x + threadIdx.x;
    if (i < n) { deg[i] = 1.0f; cnt[i] = 0; cur[i] = 0; }
}

__global__ void k_deg_hist(const int* __restrict__ col, const float* __restrict__ ew,
                           float* __restrict__ deg, int* __restrict__ cnt, int E) {
    int e = blockIdx.x * blockDim.x + threadIdx.x;
    if (e < E) {
        int c = col[e];
        atomicAdd(&deg[c], ew[e]);
        atomicAdd(&cnt[c], 1);
    }
}

__global__ void k_dinv(const float* __restrict__ deg, float* __restrict__ dinv, int n) {
    int i = blockIdx.x * blockDim.x + threadIdx.x;
    if (i < n) {
        float d = deg[i];
        dinv[i] = (d > 0.0f) ? rsqrtf(d) : 0.0f;
    }
}

// ---------------- 3-phase scan ----------------

__global__ void __launch_bounds__(SCAN_B) k_scan_local(
    const int* __restrict__ cnt, int* __restrict__ rowptr,
    int* __restrict__ bsum, int n)
{
    __shared__ int s[SCAN_B];
    const int tid = threadIdx.x;
    const int i = blockIdx.x * SCAN_B + tid;
    int v = (i < n) ? cnt[i] : 0;
    s[tid] = v;
    __syncthreads();
#pragma unroll
    for (int ofs = 1; ofs < SCAN_B; ofs <<= 1) {
        int t = (tid >= ofs) ? s[tid - ofs] : 0;
        __syncthreads();
        s[tid] += t;
        __syncthreads();
    }
    if (i < n) rowptr[i] = s[tid] - v;            // exclusive local scan
    if (tid == SCAN_B - 1) bsum[blockIdx.x] = s[tid];
}

__global__ void __launch_bounds__(MAXBLK) k_scan_mid(
    const int* __restrict__ bsum, int* __restrict__ boffs, int nb)
{
    __shared__ int s[MAXBLK];
    const int tid = threadIdx.x;
    int v = (tid < nb) ? bsum[tid] : 0;
    s[tid] = v;
    __syncthreads();
#pragma unroll
    for (int ofs = 1; ofs < MAXBLK; ofs <<= 1) {
        int t = (tid >= ofs) ? s[tid - ofs] : 0;
        __syncthreads();
        s[tid] += t;
        __syncthreads();
    }
    if (tid < nb) boffs[tid] = s[tid] - v;        // exclusive
}

__global__ void __launch_bounds__(SCAN_B) k_scan_add(
    int* __restrict__ rowptr, const int* __restrict__ boffs, int n, int E)
{
    const int i = blockIdx.x * SCAN_B + threadIdx.x;
    if (i < n) rowptr[i] += boffs[blockIdx.x];
    if (i == 0) rowptr[n] = E;
}

// ---------------- counting-sort fill ----------------

__global__ void k_fill(const int* __restrict__ row, const int* __restrict__ col,
                       const float* __restrict__ ew, const float* __restrict__ dinv,
                       const int* __restrict__ rowptr, int* __restrict__ cur,
                       int* __restrict__ srow, float* __restrict__ snorm, int E) {
    int e = blockIdx.x * blockDim.x + threadIdx.x;
    if (e >= E) return;
    int r = row[e];
    int c = col[e];
    int pos = rowptr[c] + atomicAdd(&cur[c], 1);
    srow[pos] = r;
    snorm[pos] = dinv[r] * ew[e] * dinv[c];
}

// ---------------- fp32 SGEMM ----------------

__global__ void __launch_bounds__(256) k_gemm(
    const float* __restrict__ A, const float* __restrict__ W,
    const float* __restrict__ bias, float* __restrict__ C,
    int M, int doRelu, int doBias)
{
    __shared__ float As[8][132];
    __shared__ float Bs[8][128];

    const int tid = threadIdx.x;
    const int rbase = blockIdx.x * 128;
    const int tr = tid >> 4;
    const int tc = tid & 15;

    const int arow = tid >> 1;
    const int ac4  = (tid & 1) * 4;
    const int brow = tid >> 5;
    const int bc4  = (tid & 31) * 4;
    const int grow = rbase + arow;

    float acc[8][8];
#pragma unroll
    for (int m = 0; m < 8; m++)
#pragma unroll
        for (int n = 0; n < 8; n++) acc[m][n] = 0.0f;

    for (int k0 = 0; k0 < 128; k0 += 8) {
        float4 av = make_float4(0.f, 0.f, 0.f, 0.f);
        if (grow < M)
            av = *reinterpret_cast<const float4*>(A + (size_t)grow * FDIM + k0 + ac4);
        if (doRelu) {
            av.x = fmaxf(av.x, 0.f); av.y = fmaxf(av.y, 0.f);
            av.z = fmaxf(av.z, 0.f); av.w = fmaxf(av.w, 0.f);
        }
        As[ac4 + 0][arow] = av.x;
        As[ac4 + 1][arow] = av.y;
        As[ac4 + 2][arow] = av.z;
        As[ac4 + 3][arow] = av.w;

        float4 bv = *reinterpret_cast<const float4*>(W + (size_t)(k0 + brow) * FDIM + bc4);
        *reinterpret_cast<float4*>(&Bs[brow][bc4]) = bv;

        __syncthreads();

#pragma unroll
        for (int kk = 0; kk < 8; kk++) {
            float a[8], b[8];
            float4 a0 = *reinterpret_cast<const float4*>(&As[kk][tr * 8]);
            float4 a1 = *reinterpret_cast<const float4*>(&As[kk][tr * 8 + 4]);
            float4 b0 = *reinterpret_cast<const float4*>(&Bs[kk][tc * 8]);
            float4 b1 = *reinterpret_cast<const float4*>(&Bs[kk][tc * 8 + 4]);
            a[0]=a0.x; a[1]=a0.y; a[2]=a0.z; a[3]=a0.w;
            a[4]=a1.x; a[5]=a1.y; a[6]=a1.z; a[7]=a1.w;
            b[0]=b0.x; b[1]=b0.y; b[2]=b0.z; b[3]=b0.w;
            b[4]=b1.x; b[5]=b1.y; b[6]=b1.z; b[7]=b1.w;
#pragma unroll
            for (int m = 0; m < 8; m++)
#pragma unroll
                for (int n = 0; n < 8; n++)
                    acc[m][n] = fmaf(a[m], b[n], acc[m][n]);
        }
        __syncthreads();
    }

    float bv0[8];
    if (doBias) {
#pragma unroll
        for (int n = 0; n < 8; n++) bv0[n] = bias[tc * 8 + n];
    } else {
#pragma unroll
        for (int n = 0; n < 8; n++) bv0[n] = 0.0f;
    }

#pragma unroll
    for (int m = 0; m < 8; m++) {
        int row = rbase + tr * 8 + m;
        if (row < M) {
            float4 o0, o1;
            o0.x = acc[m][0] + bv0[0]; o0.y = acc[m][1] + bv0[1];
            o0.z = acc[m][2] + bv0[2]; o0.w = acc[m][3] + bv0[3];
            o1.x = acc[m][4] + bv0[4]; o1.y = acc[m][5] + bv0[5];
            o1.z = acc[m][6] + bv0[6]; o1.w = acc[m][7] + bv0[7];
            float* cp = C + (size_t)row * FDIM + tc * 8;
            *reinterpret_cast<float4*>(cp)     = o0;
            *reinterpret_cast<float4*>(cp + 4) = o1;
        }
    }
}

// ---------------- CSR aggregate: one warp per node ----------------

__global__ void __launch_bounds__(256) k_aggregate(
    const int* __restrict__ rowptr, const int* __restrict__ srow,
    const float* __restrict__ snorm, const float* __restrict__ dinv,
    const float* __restrict__ bias, const float* __restrict__ t,
    float* __restrict__ h, int n)
{
    int node = blockIdx.x * 8 + (threadIdx.x >> 5);
    if (node >= n) return;
    const int lane = threadIdx.x & 31;
    const int f4 = lane * 4;

    float d = __ldg(dinv + node);
    float d2 = d * d;
    float4 tv = *reinterpret_cast<const float4*>(t + (size_t)node * FDIM + f4);
    float4 bv = *reinterpret_cast<const float4*>(bias + f4);
    float4 acc;
    acc.x = fmaf(tv.x, d2, bv.x);
    acc.y = fmaf(tv.y, d2, bv.y);
    acc.z = fmaf(tv.z, d2, bv.z);
    acc.w = fmaf(tv.w, d2, bv.w);

    int j = __ldg(rowptr + node);
    const int jend = __ldg(rowptr + node + 1);

    for (; j + 1 < jend; j += 2) {
        int r0 = __ldg(srow + j);
        int r1 = __ldg(srow + j + 1);
        float w0 = __ldg(snorm + j);
        float w1 = __ldg(snorm + j + 1);
        float4 v0 = *reinterpret_cast<const float4*>(t + (size_t)r0 * FDIM + f4);
        float4 v1 = *reinterpret_cast<const float4*>(t + (size_t)r1 * FDIM + f4);
        acc.x = fmaf(v0.x, w0, acc.x); acc.y = fmaf(v0.y, w0, acc.y);
        acc.z = fmaf(v0.z, w0, acc.z); acc.w = fmaf(v0.w, w0, acc.w);
        acc.x = fmaf(v1.x, w1, acc.x); acc.y = fmaf(v1.y, w1, acc.y);
        acc.z = fmaf(v1.z, w1, acc.z); acc.w = fmaf(v1.w, w1, acc.w);
    }
    if (j < jend) {
        int r0 = __ldg(srow + j);
        float w0 = __ldg(snorm + j);
        float4 v0 = *reinterpret_cast<const float4*>(t + (size_t)r0 * FDIM + f4);
        acc.x = fmaf(v0.x, w0, acc.x); acc.y = fmaf(v0.y, w0, acc.y);
        acc.z = fmaf(v0.z, w0, acc.z); acc.w = fmaf(v0.w, w0, acc.w);
    }

    *reinterpret_cast<float4*>(h + (size_t)node * FDIM + f4) = acc;
}

// ---------------- launch ----------------

extern "C" void kernel_launch(void* const* d_in, const int* in_sizes, int n_in,
                              void* d_out, int out_size) {
    const float* x    = (const float*)d_in[0];
    const int*   ei   = (const int*)  d_in[1];
    const float* ew   = (const float*)d_in[2];
    const float* Wc[4] = {(const float*)d_in[3], (const float*)d_in[5],
                          (const float*)d_in[7], (const float*)d_in[9]};
    const float* bc[4] = {(const float*)d_in[4], (const float*)d_in[6],
                          (const float*)d_in[8], (const float*)d_in[10]};
    const float* Wout = (const float*)d_in[11];
    const float* bout = (const float*)d_in[12];
    float* out = (float*)d_out;

    const int N = in_sizes[0] / FDIM;
    const int E = in_sizes[2];
    const int* rowp = ei;
    const int* colp = ei + E;

    float *t, *h, *deg, *dinv, *snorm;
    int *cnt, *rowptr, *cur, *srow, *bsum, *boffs;
    cudaGetSymbolAddress((void**)&t, g_t);
    cudaGetSymbolAddress((void**)&h, g_h);
    cudaGetSymbolAddress((void**)&deg, g_deg);
    cudaGetSymbolAddress((void**)&dinv, g_dinv);
    cudaGetSymbolAddress((void**)&cnt, g_cnt);
    cudaGetSymbolAddress((void**)&rowptr, g_rowptr);
    cudaGetSymbolAddress((void**)&cur, g_cursor);
    cudaGetSymbolAddress((void**)&srow, g_srow);
    cudaGetSymbolAddress((void**)&snorm, g_snorm);
    cudaGetSymbolAddress((void**)&bsum, g_bsum);
    cudaGetSymbolAddress((void**)&boffs, g_boffs);

    const int TB = 256;
    const int nScanBlk = (N + SCAN_B - 1) / SCAN_B;

    // one-time CSR build
    k_init<<<(N + TB - 1) / TB, TB>>>(deg, cnt, cur, N);
    k_deg_hist<<<(E + TB - 1) / TB, TB>>>(colp, ew, deg, cnt, E);
    k_dinv<<<(N + TB - 1) / TB, TB>>>(deg, dinv, N);
    k_scan_local<<<nScanBlk, SCAN_B>>>(cnt, rowptr, bsum, N);
    k_scan_mid<<<1, MAXBLK>>>(bsum, boffs, nScanBlk);
    k_scan_add<<<nScanBlk, SCAN_B>>>(rowptr, boffs, N, E);
    k_fill<<<(E + TB - 1) / TB, TB>>>(rowp, colp, ew, dinv, rowptr, cur, srow, snorm, E);

    const int gemmBlocks = (N + 127) / 128;
    const int aggBlocks  = (N + 7) / 8;

    for (int l = 0; l < 4; l++) {
        const float* src = (l == 0) ? x : h;
        int relu = (l == 0) ? 0 : 1;
        k_gemm<<<gemmBlocks, TB>>>(src, Wc[l], nullptr, t, N, relu, 0);
        k_aggregate<<<aggBlocks, TB>>>(rowptr, srow, snorm, dinv, bc[l], t, h, N);
    }

    k_gemm<<<gemmBlocks, TB>>>(h, Wout, bout, out, N, 0, 1);
}

// round 5
// speedup vs baseline: 1.7765x; 1.0140x over previous
#include <cuda_runtime.h>
#include <cuda_bf16.h>
#include <cstdint>

// ---------------------------------------------------------------------------
// GCN: 4x GCNConv(128->128) + output linear(128->128), N=100000, E=1600000.
// Round 5: mma.sync bf16x3 split GEMM (tcgen05 unavailable: toolchain emits
// compute_103 PTX without the 'a' feature set). CSR aggregate unchanged.
// ---------------------------------------------------------------------------

#define NMAX 100096
#define EMAX 1600000
#define FDIM 128
#define SCAN_B 1024
#define MAXBLK 128
#define ASTRIDE 136   // bf16 elements per smem row (272B -> conflict-free ldmatrix)

__device__ float g_t[(size_t)NMAX * FDIM];
__device__ float g_h[(size_t)NMAX * FDIM];
__device__ float g_deg[NMAX];
__device__ float g_dinv[NMAX];
__device__ int   g_cnt[NMAX];
__device__ int   g_rowptr[NMAX + 1];
__device__ int   g_cursor[NMAX];
__device__ int   g_srow[EMAX];
__device__ float g_snorm[EMAX];
__device__ int   g_bsum[MAXBLK];
__device__ int   g_boffs[MAXBLK];
// pre-split weights as bf16, [n][k] K-major (B operand layout), 32KB each
__device__ __align__(16) __nv_bfloat16 g_whi[5 * 16384];
__device__ __align__(16) __nv_bfloat16 g_wlo[5 * 16384];

// ---------------- helpers ----------------

__device__ __forceinline__ uint32_t smem_u32(const void* p) {
    uint32_t a;
    asm("{ .reg .u64 t; cvta.to.shared.u64 t, %1; cvt.u32.u64 %0, t; }" : "=r"(a) : "l"(p));
    return a;
}

__device__ __forceinline__ void ldsm4(uint32_t& r0, uint32_t& r1, uint32_t& r2,
                                      uint32_t& r3, uint32_t addr) {
    asm volatile("ldmatrix.sync.aligned.m8n8.x4.shared.b16 {%0,%1,%2,%3}, [%4];"
                 : "=r"(r0), "=r"(r1), "=r"(r2), "=r"(r3) : "r"(addr));
}

__device__ __forceinline__ void mma16816(float* c, uint32_t a0, uint32_t a1,
                                         uint32_t a2, uint32_t a3,
                                         uint32_t b0, uint32_t b1) {
    asm volatile(
        "mma.sync.aligned.m16n8k16.row.col.f32.bf16.bf16.f32 "
        "{%0,%1,%2,%3}, {%4,%5,%6,%7}, {%8,%9}, {%0,%1,%2,%3};"
        : "+f"(c[0]), "+f"(c[1]), "+f"(c[2]), "+f"(c[3])
        : "r"(a0), "r"(a1), "r"(a2), "r"(a3), "r"(b0), "r"(b1));
}

// ---------------- degree + histogram ----------------

__global__ void k_init(float* __restrict__ deg, int* __restrict__ cnt,
                       int* __restrict__ cur, int n) {
    int i = blockIdx.x * blockDim.x + threadIdx.x;
    if (i < n) { deg[i] = 1.0f; cnt[i] = 0; cur[i] = 0; }
}

__global__ void k_deg_hist(const int* __restrict__ col, const float* __restrict__ ew,
                           float* __restrict__ deg, int* __restrict__ cnt, int E) {
    int e = blockIdx.x * blockDim.x + threadIdx.x;
    if (e < E) {
        int c = col[e];
        atomicAdd(&deg[c], ew[e]);
        atomicAdd(&cnt[c], 1);
    }
}

__global__ void k_dinv(const float* __restrict__ deg, float* __restrict__ dinv, int n) {
    int i = blockIdx.x * blockDim.x + threadIdx.x;
    if (i < n) {
        float d = deg[i];
        dinv[i] = (d > 0.0f) ? rsqrtf(d) : 0.0f;
    }
}

// ---------------- 3-phase scan ----------------

__global__ void __launch_bounds__(SCAN_B) k_scan_local(
    const int* __restrict__ cnt, int* __restrict__ rowptr,
    int* __restrict__ bsum, int n)
{
    __shared__ int s[SCAN_B];
    const int tid = threadIdx.x;
    const int i = blockIdx.x * SCAN_B + tid;
    int v = (i < n) ? cnt[i] : 0;
    s[tid] = v;
    __syncthreads();
#pragma unroll
    for (int ofs = 1; ofs < SCAN_B; ofs <<= 1) {
        int t = (tid >= ofs) ? s[tid - ofs] : 0;
        __syncthreads();
        s[tid] += t;
        __syncthreads();
    }
    if (i < n) rowptr[i] = s[tid] - v;
    if (tid == SCAN_B - 1) bsum[blockIdx.x] = s[tid];
}

__global__ void __launch_bounds__(MAXBLK) k_scan_mid(
    const int* __restrict__ bsum, int* __restrict__ boffs, int nb)
{
    __shared__ int s[MAXBLK];
    const int tid = threadIdx.x;
    int v = (tid < nb) ? bsum[tid] : 0;
    s[tid] = v;
    __syncthreads();
#pragma unroll
    for (int ofs = 1; ofs < MAXBLK; ofs <<= 1) {
        int t = (tid >= ofs) ? s[tid - ofs] : 0;
        __syncthreads();
        s[tid] += t;
        __syncthreads();
    }
    if (tid < nb) boffs[tid] = s[tid] - v;
}

__global__ void __launch_bounds__(SCAN_B) k_scan_add(
    int* __restrict__ rowptr, const int* __restrict__ boffs, int n, int E)
{
    const int i = blockIdx.x * SCAN_B + threadIdx.x;
    if (i < n) rowptr[i] += boffs[blockIdx.x];
    if (i == 0) rowptr[n] = E;
}

// ---------------- counting-sort fill ----------------

__global__ void k_fill(const int* __restrict__ row, const int* __restrict__ col,
                       const float* __restrict__ ew, const float* __restrict__ dinv,
                       const int* __restrict__ rowptr, int* __restrict__ cur,
                       int* __restrict__ srow, float* __restrict__ snorm, int E) {
    int e = blockIdx.x * blockDim.x + threadIdx.x;
    if (e >= E) return;
    int r = row[e];
    int c = col[e];
    int pos = rowptr[c] + atomicAdd(&cur[c], 1);
    srow[pos] = r;
    snorm[pos] = dinv[r] * ew[e] * dinv[c];
}

// ---------------- weight prep: split W into hi/lo bf16, [n][k] K-major ----------------

__global__ void k_wprep(const float* __restrict__ W, __nv_bfloat16* __restrict__ dhi,
                        __nv_bfloat16* __restrict__ dlo) {
    int idx = blockIdx.x * blockDim.x + threadIdx.x;
    if (idx >= 16384) return;
    int n = idx >> 7, k = idx & 127;
    float w = W[k * 128 + n];                 // B[n][k] = W[k][n]
    __nv_bfloat16 hi = __float2bfloat16(w);
    __nv_bfloat16 lo = __float2bfloat16(w - __bfloat162float(hi));
    dhi[n * 128 + k] = hi;
    dlo[n * 128 + k] = lo;
}

// ---------------- HMMA GEMM: C[M,128] = act(A[M,128]) @ W (+bias) ----------------
// bf16x3 split: Ahi*Whi + Alo*Whi + Ahi*Wlo. 8 warps: 4 row-groups x 2 col-groups.

__global__ void __launch_bounds__(256) k_gemm_mma(
    const float* __restrict__ A, const __nv_bfloat16* __restrict__ whi,
    const __nv_bfloat16* __restrict__ wlo, const float* __restrict__ bias,
    float* __restrict__ C, int M, int doRelu, int doBias)
{
    extern __shared__ __nv_bfloat16 sm[];
    __nv_bfloat16* sAhi = sm;
    __nv_bfloat16* sAlo = sm + 128 * ASTRIDE;
    __nv_bfloat16* sWhi = sm + 2 * 128 * ASTRIDE;
    __nv_bfloat16* sWlo = sm + 3 * 128 * ASTRIDE;

    const int tid = threadIdx.x;
    const int wid = tid >> 5;
    const int lane = tid & 31;
    const int rbase = blockIdx.x * 128;

    // ---- stage W (hi/lo) into smem, stride change 128 -> ASTRIDE ----
    {
        const uint4* shi = reinterpret_cast<const uint4*>(whi);
        const uint4* slo = reinterpret_cast<const uint4*>(wlo);
        for (int i = tid; i < 2048; i += 256) {   // 128 rows x 16 uint4
            int r = i >> 4, q = i & 15;
            *reinterpret_cast<uint4*>(sWhi + r * ASTRIDE + q * 8) = shi[i];
            *reinterpret_cast<uint4*>(sWlo + r * ASTRIDE + q * 8) = slo[i];
        }
    }

    // ---- convert A tile to hi/lo bf16 ----
    for (int idx = tid; idx < 4096; idx += 256) {
        int row = idx >> 5;
        int c4 = (idx & 31) << 2;
        int grow = rbase + row;
        float4 av = make_float4(0.f, 0.f, 0.f, 0.f);
        if (grow < M)
            av = *reinterpret_cast<const float4*>(A + (size_t)grow * FDIM + c4);
        if (doRelu) {
            av.x = fmaxf(av.x, 0.f); av.y = fmaxf(av.y, 0.f);
            av.z = fmaxf(av.z, 0.f); av.w = fmaxf(av.w, 0.f);
        }
        __nv_bfloat162 h01, h23, l01, l23;
        h01.x = __float2bfloat16(av.x);
        h01.y = __float2bfloat16(av.y);
        h23.x = __float2bfloat16(av.z);
        h23.y = __float2bfloat16(av.w);
        l01.x = __float2bfloat16(av.x - __bfloat162float(h01.x));
        l01.y = __float2bfloat16(av.y - __bfloat162float(h01.y));
        l23.x = __float2bfloat16(av.z - __bfloat162float(h23.x));
        l23.y = __float2bfloat16(av.w - __bfloat162float(h23.y));
        int off = row * ASTRIDE + c4;
        *reinterpret_cast<uint32_t*>(sAhi + off)     = *reinterpret_cast<uint32_t*>(&h01);
        *reinterpret_cast<uint32_t*>(sAhi + off + 2) = *reinterpret_cast<uint32_t*>(&h23);
        *reinterpret_cast<uint32_t*>(sAlo + off)     = *reinterpret_cast<uint32_t*>(&l01);
        *reinterpret_cast<uint32_t*>(sAlo + off + 2) = *reinterpret_cast<uint32_t*>(&l23);
    }
    __syncthreads();

    // ---- mainloop ----
    const int warpRow = (wid & 3) * 32;   // row group of 32
    const int warpCol = (wid >> 2) * 64;  // col group of 64

    // ldmatrix lane address components
    const int a_r = lane & 15;            // row within 16-row tile
    const int a_c = (lane >> 4) << 3;     // 0 or 8 (k)
    const int b_n = (lane & 7) + ((lane >> 4) << 3);   // n within 16
    const int b_k = ((lane >> 3) & 1) << 3;            // 0 or 8 (k)

    const uint32_t uAhi = smem_u32(sAhi);
    const uint32_t uAlo = smem_u32(sAlo);
    const uint32_t uWhi = smem_u32(sWhi);
    const uint32_t uWlo = smem_u32(sWlo);
    const uint32_t aTerm[3] = {uAhi, uAlo, uAhi};
    const uint32_t bTerm[3] = {uWhi, uWhi, uWlo};

    float c[2][8][4];
#pragma unroll
    for (int mi = 0; mi < 2; mi++)
#pragma unroll
        for (int ni = 0; ni < 8; ni++)
#pragma unroll
            for (int q = 0; q < 4; q++) c[mi][ni][q] = 0.0f;

#pragma unroll
    for (int t = 0; t < 3; t++) {
        const uint32_t ab = aTerm[t];
        const uint32_t bb = bTerm[t];
#pragma unroll
        for (int k0 = 0; k0 < 128; k0 += 16) {
            uint32_t a0[4], a1[4];
            ldsm4(a0[0], a0[1], a0[2], a0[3],
                  ab + (uint32_t)(((warpRow + a_r) * ASTRIDE + k0 + a_c) * 2));
            ldsm4(a1[0], a1[1], a1[2], a1[3],
                  ab + (uint32_t)(((warpRow + 16 + a_r) * ASTRIDE + k0 + a_c) * 2));
#pragma unroll
            for (int nj = 0; nj < 4; nj++) {
                uint32_t b[4];
                ldsm4(b[0], b[1], b[2], b[3],
                      bb + (uint32_t)(((warpCol + nj * 16 + b_n) * ASTRIDE + k0 + b_k) * 2));
                mma16816(c[0][nj * 2],     a0[0], a0[1], a0[2], a0[3], b[0], b[1]);
                mma16816(c[0][nj * 2 + 1], a0[0], a0[1], a0[2], a0[3], b[2], b[3]);
                mma16816(c[1][nj * 2],     a1[0], a1[1], a1[2], a1[3], b[0], b[1]);
                mma16816(c[1][nj * 2 + 1], a1[0], a1[1], a1[2], a1[3], b[2], b[3]);
            }
        }
    }

    // ---- epilogue: direct float2 stores ----
    const int crow = lane >> 2;           // 0..7
    const int ccol = (lane & 3) * 2;      // 0,2,4,6
#pragma unroll
    for (int mi = 0; mi < 2; mi++) {
#pragma unroll
        for (int ni = 0; ni < 8; ni++) {
            int colg = warpCol + ni * 8 + ccol;
            float bx = 0.f, by = 0.f;
            if (doBias) { bx = bias[colg]; by = bias[colg + 1]; }
            int r0 = rbase + warpRow + mi * 16 + crow;
            int r1 = r0 + 8;
            if (r0 < M) {
                float2 v = make_float2(c[mi][ni][0] + bx, c[mi][ni][1] + by);
                *reinterpret_cast<float2*>(C + (size_t)r0 * FDIM + colg) = v;
            }
            if (r1 < M) {
                float2 v = make_float2(c[mi][ni][2] + bx, c[mi][ni][3] + by);
                *reinterpret_cast<float2*>(C + (size_t)r1 * FDIM + colg) = v;
            }
        }
    }
}

// ---------------- CSR aggregate: one warp per node ----------------

__global__ void __launch_bounds__(256) k_aggregate(
    const int* __restrict__ rowptr, const int* __restrict__ srow,
    const float* __restrict__ snorm, const float* __restrict__ dinv,
    const float* __restrict__ bias, const float* __restrict__ t,
    float* __restrict__ h, int n)
{
    int node = blockIdx.x * 8 + (threadIdx.x >> 5);
    if (node >= n) return;
    const int lane = threadIdx.x & 31;
    const int f4 = lane * 4;

    float d = __ldg(dinv + node);
    float d2 = d * d;
    float4 tv = *reinterpret_cast<const float4*>(t + (size_t)node * FDIM + f4);
    float4 bv = *reinterpret_cast<const float4*>(bias + f4);
    float4 acc;
    acc.x = fmaf(tv.x, d2, bv.x);
    acc.y = fmaf(tv.y, d2, bv.y);
    acc.z = fmaf(tv.z, d2, bv.z);
    acc.w = fmaf(tv.w, d2, bv.w);

    int j = __ldg(rowptr + node);
    const int jend = __ldg(rowptr + node + 1);

    for (; j + 1 < jend; j += 2) {
        int r0 = __ldg(srow + j);
        int r1 = __ldg(srow + j + 1);
        float w0 = __ldg(snorm + j);
        float w1 = __ldg(snorm + j + 1);
        float4 v0 = *reinterpret_cast<const float4*>(t + (size_t)r0 * FDIM + f4);
        float4 v1 = *reinterpret_cast<const float4*>(t + (size_t)r1 * FDIM + f4);
        acc.x = fmaf(v0.x, w0, acc.x); acc.y = fmaf(v0.y, w0, acc.y);
        acc.z = fmaf(v0.z, w0, acc.z); acc.w = fmaf(v0.w, w0, acc.w);
        acc.x = fmaf(v1.x, w1, acc.x); acc.y = fmaf(v1.y, w1, acc.y);
        acc.z = fmaf(v1.z, w1, acc.z); acc.w = fmaf(v1.w, w1, acc.w);
    }
    if (j < jend) {
        int r0 = __ldg(srow + j);
        float w0 = __ldg(snorm + j);
        float4 v0 = *reinterpret_cast<const float4*>(t + (size_t)r0 * FDIM + f4);
        acc.x = fmaf(v0.x, w0, acc.x); acc.y = fmaf(v0.y, w0, acc.y);
        acc.z = fmaf(v0.z, w0, acc.z); acc.w = fmaf(v0.w, w0, acc.w);
    }

    *reinterpret_cast<float4*>(h + (size_t)node * FDIM + f4) = acc;
}

// ---------------- launch ----------------

extern "C" void kernel_launch(void* const* d_in, const int* in_sizes, int n_in,
                              void* d_out, int out_size) {
    const float* x    = (const float*)d_in[0];
    const int*   ei   = (const int*)  d_in[1];
    const float* ew   = (const float*)d_in[2];
    const float* Wc[4] = {(const float*)d_in[3], (const float*)d_in[5],
                          (const float*)d_in[7], (const float*)d_in[9]};
    const float* bc[4] = {(const float*)d_in[4], (const float*)d_in[6],
                          (const float*)d_in[8], (const float*)d_in[10]};
    const float* Wout = (const float*)d_in[11];
    const float* bout = (const float*)d_in[12];
    float* out = (float*)d_out;

    const int N = in_sizes[0] / FDIM;
    const int E = in_sizes[2];
    const int* rowp = ei;
    const int* colp = ei + E;

    float *t, *h, *deg, *dinv, *snorm;
    int *cnt, *rowptr, *cur, *srow, *bsum, *boffs;
    __nv_bfloat16 *whi, *wlo;
    cudaGetSymbolAddress((void**)&t, g_t);
    cudaGetSymbolAddress((void**)&h, g_h);
    cudaGetSymbolAddress((void**)&deg, g_deg);
    cudaGetSymbolAddress((void**)&dinv, g_dinv);
    cudaGetSymbolAddress((void**)&cnt, g_cnt);
    cudaGetSymbolAddress((void**)&rowptr, g_rowptr);
    cudaGetSymbolAddress((void**)&cur, g_cursor);
    cudaGetSymbolAddress((void**)&srow, g_srow);
    cudaGetSymbolAddress((void**)&snorm, g_snorm);
    cudaGetSymbolAddress((void**)&bsum, g_bsum);
    cudaGetSymbolAddress((void**)&boffs, g_boffs);
    cudaGetSymbolAddress((void**)&whi, g_whi);
    cudaGetSymbolAddress((void**)&wlo, g_wlo);

    static const int SMEM_DYN = 4 * 128 * ASTRIDE * 2;   // 139264 B
    cudaFuncSetAttribute(k_gemm_mma, cudaFuncAttributeMaxDynamicSharedMemorySize, SMEM_DYN);

    const int TB = 256;
    const int nScanBlk = (N + SCAN_B - 1) / SCAN_B;

    // one-time CSR build + weight split
    k_init<<<(N + TB - 1) / TB, TB>>>(deg, cnt, cur, N);
    k_deg_hist<<<(E + TB - 1) / TB, TB>>>(colp, ew, deg, cnt, E);
    k_dinv<<<(N + TB - 1) / TB, TB>>>(deg, dinv, N);
    k_scan_local<<<nScanBlk, SCAN_B>>>(cnt, rowptr, bsum, N);
    k_scan_mid<<<1, MAXBLK>>>(bsum, boffs, nScanBlk);
    k_scan_add<<<nScanBlk, SCAN_B>>>(rowptr, boffs, N, E);
    k_fill<<<(E + TB - 1) / TB, TB>>>(rowp, colp, ew, dinv, rowptr, cur, srow, snorm, E);

    const int wpBlocks = (16384 + TB - 1) / TB;
    for (int l = 0; l < 4; l++)
        k_wprep<<<wpBlocks, TB>>>(Wc[l], whi + l * 16384, wlo + l * 16384);
    k_wprep<<<wpBlocks, TB>>>(Wout, whi + 4 * 16384, wlo + 4 * 16384);

    const int gemmBlocks = (N + 127) / 128;
    const int aggBlocks  = (N + 7) / 8;

    for (int l = 0; l < 4; l++) {
        const float* src = (l == 0) ? x : h;
        int relu = (l == 0) ? 0 : 1;
        k_gemm_mma<<<gemmBlocks, TB, SMEM_DYN>>>(src, whi + l * 16384, wlo + l * 16384,
                                                 nullptr, t, N, relu, 0);
        k_aggregate<<<aggBlocks, TB>>>(rowptr, srow, snorm, dinv, bc[l], t, h, N);
    }

    k_gemm_mma<<<gemmBlocks, TB, SMEM_DYN>>>(h, whi + 4 * 16384, wlo + 4 * 16384,
                                             bout, out, N, 0, 1);
}

// round 6
// speedup vs baseline: 2.1603x; 1.2161x over previous
#include <cuda_runtime.h>
#include <cuda_bf16.h>
#include <cstdint>

// ---------------------------------------------------------------------------
// GCN: 4x GCNConv(128->128) + output linear(128->128), N=100000, E=1600000.
// Round 6: HMMA GEMM rebuilt for occupancy (BM=64, XOR swizzle, 96KB smem ->
// 2 CTAs/SM, cp.async W staging). Launches reordered so ncu (-s 5 -c 1)
// captures k_gemm_mma as the 6th launch.
// ---------------------------------------------------------------------------

#define NMAX 100096
#define EMAX 1600000
#define FDIM 128
#define SCAN_B 1024
#define MAXBLK 128
#define BM 64

__device__ float g_t[(size_t)NMAX * FDIM];
__device__ float g_h[(size_t)NMAX * FDIM];
__device__ float g_deg[NMAX];
__device__ float g_dinv[NMAX];
__device__ int   g_cnt[NMAX];
__device__ int   g_rowptr[NMAX + 1];
__device__ int   g_cursor[NMAX];
__device__ int   g_srow[EMAX];
__device__ float g_snorm[EMAX];
__device__ int   g_bsum[MAXBLK];
__device__ int   g_boffs[MAXBLK];
// pre-split weights bf16, [n][k] K-major, 32KB each
__device__ __align__(16) __nv_bfloat16 g_whi[5 * 16384];
__device__ __align__(16) __nv_bfloat16 g_wlo[5 * 16384];

// ---------------- helpers ----------------

__device__ __forceinline__ uint32_t smem_u32(const void* p) {
    uint32_t a;
    asm("{ .reg .u64 t; cvta.to.shared.u64 t, %1; cvt.u32.u64 %0, t; }" : "=r"(a) : "l"(p));
    return a;
}

__device__ __forceinline__ void ldsm4(uint32_t& r0, uint32_t& r1, uint32_t& r2,
                                      uint32_t& r3, uint32_t addr) {
    asm volatile("ldmatrix.sync.aligned.m8n8.x4.shared.b16 {%0,%1,%2,%3}, [%4];"
                 : "=r"(r0), "=r"(r1), "=r"(r2), "=r"(r3) : "r"(addr));
}

__device__ __forceinline__ void mma16816(float* c, uint32_t a0, uint32_t a1,
                                         uint32_t a2, uint32_t a3,
                                         uint32_t b0, uint32_t b1) {
    asm volatile(
        "mma.sync.aligned.m16n8k16.row.col.f32.bf16.bf16.f32 "
        "{%0,%1,%2,%3}, {%4,%5,%6,%7}, {%8,%9}, {%0,%1,%2,%3};"
        : "+f"(c[0]), "+f"(c[1]), "+f"(c[2]), "+f"(c[3])
        : "r"(a0), "r"(a1), "r"(a2), "r"(a3), "r"(b0), "r"(b1));
}

__device__ __forceinline__ void cp16(uint32_t dst, const void* src) {
    asm volatile("cp.async.ca.shared.global [%0], [%1], 16;" :: "r"(dst), "l"(src));
}

// XOR-swizzled layout: 256B rows (128 bf16), 16B chunk c swizzled by row low bits.
// addr(r, k) for bf16 element: r*256 + ((k>>3) ^ (r&7))*16 + (k&7)*2
__device__ __forceinline__ uint32_t swz(int r, int k) {
    return (uint32_t)((r << 8) + ((((k >> 3) ^ (r & 7)) << 4)) + ((k & 7) << 1));
}

// ---------------- degree + histogram ----------------

__global__ void k_init(float* __restrict__ deg, int* __restrict__ cnt,
                       int* __restrict__ cur, int n) {
    int i = blockIdx.x * blockDim.x + threadIdx.x;
    if (i < n) { deg[i] = 1.0f; cnt[i] = 0; cur[i] = 0; }
}

__global__ void k_deg_hist(const int* __restrict__ col, const float* __restrict__ ew,
                           float* __restrict__ deg, int* __restrict__ cnt, int E) {
    int e = blockIdx.x * blockDim.x + threadIdx.x;
    if (e < E) {
        int c = col[e];
        atomicAdd(&deg[c], ew[e]);
        atomicAdd(&cnt[c], 1);
    }
}

__global__ void k_dinv(const float* __restrict__ deg, float* __restrict__ dinv, int n) {
    int i = blockIdx.x * blockDim.x + threadIdx.x;
    if (i < n) {
        float d = deg[i];
        dinv[i] = (d > 0.0f) ? rsqrtf(d) : 0.0f;
    }
}

// ---------------- 3-phase scan ----------------

__global__ void __launch_bounds__(SCAN_B) k_scan_local(
    const int* __restrict__ cnt, int* __restrict__ rowptr,
    int* __restrict__ bsum, int n)
{
    __shared__ int s[SCAN_B];
    const int tid = threadIdx.x;
    const int i = blockIdx.x * SCAN_B + tid;
    int v = (i < n) ? cnt[i] : 0;
    s[tid] = v;
    __syncthreads();
#pragma unroll
    for (int ofs = 1; ofs < SCAN_B; ofs <<= 1) {
        int t = (tid >= ofs) ? s[tid - ofs] : 0;
        __syncthreads();
        s[tid] += t;
        __syncthreads();
    }
    if (i < n) rowptr[i] = s[tid] - v;
    if (tid == SCAN_B - 1) bsum[blockIdx.x] = s[tid];
}

__global__ void __launch_bounds__(MAXBLK) k_scan_mid(
    const int* __restrict__ bsum, int* __restrict__ boffs, int nb)
{
    __shared__ int s[MAXBLK];
    const int tid = threadIdx.x;
    int v = (tid < nb) ? bsum[tid] : 0;
    s[tid] = v;
    __syncthreads();
#pragma unroll
    for (int ofs = 1; ofs < MAXBLK; ofs <<= 1) {
        int t = (tid >= ofs) ? s[tid - ofs] : 0;
        __syncthreads();
        s[tid] += t;
        __syncthreads();
    }
    if (tid < nb) boffs[tid] = s[tid] - v;
}

__global__ void __launch_bounds__(SCAN_B) k_scan_add(
    int* __restrict__ rowptr, const int* __restrict__ boffs, int n, int E)
{
    const int i = blockIdx.x * SCAN_B + threadIdx.x;
    if (i < n) rowptr[i] += boffs[blockIdx.x];
    if (i == 0) rowptr[n] = E;
}

// ---------------- counting-sort fill ----------------

__global__ void k_fill(const int* __restrict__ row, const int* __restrict__ col,
                       const float* __restrict__ ew, const float* __restrict__ dinv,
                       const int* __restrict__ rowptr, int* __restrict__ cur,
                       int* __restrict__ srow, float* __restrict__ snorm, int E) {
    int e = blockIdx.x * blockDim.x + threadIdx.x;
    if (e >= E) return;
    int r = row[e];
    int c = col[e];
    int pos = rowptr[c] + atomicAdd(&cur[c], 1);
    srow[pos] = r;
    snorm[pos] = dinv[r] * ew[e] * dinv[c];
}

// ---------------- weight prep ----------------

__global__ void k_wprep(const float* __restrict__ W, __nv_bfloat16* __restrict__ dhi,
                        __nv_bfloat16* __restrict__ dlo) {
    int idx = blockIdx.x * blockDim.x + threadIdx.x;
    if (idx >= 16384) return;
    int n = idx >> 7, k = idx & 127;
    float w = W[k * 128 + n];                 // B[n][k] = W[k][n]
    __nv_bfloat16 hi = __float2bfloat16(w);
    __nv_bfloat16 lo = __float2bfloat16(w - __bfloat162float(hi));
    dhi[n * 128 + k] = hi;
    dlo[n * 128 + k] = lo;
}

// ---------------- HMMA GEMM: C[M,128] = act(A[M,128]) @ W (+bias) ----------------
// BM=64, 8 warps in 2x4 (row x col), XOR-swizzled smem, cp.async W staging.

__global__ void __launch_bounds__(256, 2) k_gemm_mma(
    const float* __restrict__ A, const __nv_bfloat16* __restrict__ whi,
    const __nv_bfloat16* __restrict__ wlo, const float* __restrict__ bias,
    float* __restrict__ C, int M, int doRelu, int doBias)
{
    extern __shared__ char sm[];
    char* sAhi = sm;                  // 64 rows x 256B = 16KB
    char* sAlo = sm + 16384;          // 16KB
    char* sWhi = sm + 32768;          // 128 rows x 256B = 32KB
    char* sWlo = sm + 65536;          // 32KB

    const int tid = threadIdx.x;
    const int wid = tid >> 5;
    const int lane = tid & 31;
    const int rbase = blockIdx.x * BM;

    const uint32_t uWhi = smem_u32(sWhi);
    const uint32_t uWlo = smem_u32(sWlo);
    const uint32_t uAhi = smem_u32(sAhi);
    const uint32_t uAlo = smem_u32(sAlo);

    // ---- W staging via cp.async (overlaps with A convert below) ----
    for (int i = tid; i < 2048; i += 256) {   // 128 rows x 16 chunks, per buffer
        int r = i >> 4, c = i & 15;
        uint32_t doff = (uint32_t)((r << 8) + ((c ^ (r & 7)) << 4));
        cp16(uWhi + doff, whi + r * 128 + c * 8);
        cp16(uWlo + doff, wlo + r * 128 + c * 8);
    }
    asm volatile("cp.async.commit_group;" ::: "memory");

    // ---- A convert: fp32 -> hi/lo bf16, swizzled ----
    for (int idx = tid; idx < BM * 32; idx += 256) {   // 64 rows x 32 float4
        int row = idx >> 5;
        int c4 = (idx & 31) << 2;
        int grow = rbase + row;
        float4 av = make_float4(0.f, 0.f, 0.f, 0.f);
        if (grow < M)
            av = *reinterpret_cast<const float4*>(A + (size_t)grow * FDIM + c4);
        if (doRelu) {
            av.x = fmaxf(av.x, 0.f); av.y = fmaxf(av.y, 0.f);
            av.z = fmaxf(av.z, 0.f); av.w = fmaxf(av.w, 0.f);
        }
        __nv_bfloat162 h01, h23, l01, l23;
        h01.x = __float2bfloat16(av.x);
        h01.y = __float2bfloat16(av.y);
        h23.x = __float2bfloat16(av.z);
        h23.y = __float2bfloat16(av.w);
        l01.x = __float2bfloat16(av.x - __bfloat162float(h01.x));
        l01.y = __float2bfloat16(av.y - __bfloat162float(h01.y));
        l23.x = __float2bfloat16(av.z - __bfloat162float(h23.x));
        l23.y = __float2bfloat16(av.w - __bfloat162float(h23.y));
        uint32_t off = swz(row, c4);    // c4%8==0 or 4 -> stays inside one 16B chunk
        *reinterpret_cast<uint32_t*>(sAhi + off)     = *reinterpret_cast<uint32_t*>(&h01);
        *reinterpret_cast<uint32_t*>(sAhi + off + 4) = *reinterpret_cast<uint32_t*>(&h23);
        *reinterpret_cast<uint32_t*>(sAlo + off)     = *reinterpret_cast<uint32_t*>(&l01);
        *reinterpret_cast<uint32_t*>(sAlo + off + 4) = *reinterpret_cast<uint32_t*>(&l23);
    }
    asm volatile("cp.async.wait_group 0;" ::: "memory");
    __syncthreads();

    // ---- mainloop ----
    const int warpRow = (wid & 1) * 32;
    const int warpCol = (wid >> 1) * 32;

    const int a_r = lane & 15;
    const int a_k = (lane >> 4) << 3;
    const int b_n = (lane & 7) + ((lane >> 4) << 3);
    const int b_k = ((lane >> 3) & 1) << 3;

    const uint32_t aTerm[3] = {uAhi, uAlo, uAhi};
    const uint32_t bTerm[3] = {uWhi, uWhi, uWlo};

    float c[2][4][4];
#pragma unroll
    for (int mi = 0; mi < 2; mi++)
#pragma unroll
        for (int ni = 0; ni < 4; ni++)
#pragma unroll
            for (int q = 0; q < 4; q++) c[mi][ni][q] = 0.0f;

#pragma unroll
    for (int t = 0; t < 3; t++) {
        const uint32_t ab = aTerm[t];
        const uint32_t bb = bTerm[t];
#pragma unroll
        for (int k0 = 0; k0 < 128; k0 += 16) {
            uint32_t a0[4], a1[4], b0[4], b1[4];
            ldsm4(a0[0], a0[1], a0[2], a0[3], ab + swz(warpRow + a_r,      k0 + a_k));
            ldsm4(a1[0], a1[1], a1[2], a1[3], ab + swz(warpRow + 16 + a_r, k0 + a_k));
            ldsm4(b0[0], b0[1], b0[2], b0[3], bb + swz(warpCol + b_n,      k0 + b_k));
            ldsm4(b1[0], b1[1], b1[2], b1[3], bb + swz(warpCol + 16 + b_n, k0 + b_k));
            mma16816(c[0][0], a0[0], a0[1], a0[2], a0[3], b0[0], b0[1]);
            mma16816(c[0][1], a0[0], a0[1], a0[2], a0[3], b0[2], b0[3]);
            mma16816(c[0][2], a0[0], a0[1], a0[2], a0[3], b1[0], b1[1]);
            mma16816(c[0][3], a0[0], a0[1], a0[2], a0[3], b1[2], b1[3]);
            mma16816(c[1][0], a1[0], a1[1], a1[2], a1[3], b0[0], b0[1]);
            mma16816(c[1][1], a1[0], a1[1], a1[2], a1[3], b0[2], b0[3]);
            mma16816(c[1][2], a1[0], a1[1], a1[2], a1[3], b1[0], b1[1]);
            mma16816(c[1][3], a1[0], a1[1], a1[2], a1[3], b1[2], b1[3]);
        }
    }

    // ---- epilogue ----
    const int crow = lane >> 2;
    const int ccol = (lane & 3) * 2;
#pragma unroll
    for (int mi = 0; mi < 2; mi++) {
#pragma unroll
        for (int ni = 0; ni < 4; ni++) {
            int colg = warpCol + ni * 8 + ccol;
            float bx = 0.f, by = 0.f;
            if (doBias) { bx = bias[colg]; by = bias[colg + 1]; }
            int r0 = rbase + warpRow + mi * 16 + crow;
            int r1 = r0 + 8;
            if (r0 < M) {
                float2 v = make_float2(c[mi][ni][0] + bx, c[mi][ni][1] + by);
                *reinterpret_cast<float2*>(C + (size_t)r0 * FDIM + colg) = v;
            }
            if (r1 < M) {
                float2 v = make_float2(c[mi][ni][2] + bx, c[mi][ni][3] + by);
                *reinterpret_cast<float2*>(C + (size_t)r1 * FDIM + colg) = v;
            }
        }
    }
}

// ---------------- CSR aggregate: one warp per node ----------------

__global__ void __launch_bounds__(256) k_aggregate(
    const int* __restrict__ rowptr, const int* __restrict__ srow,
    const float* __restrict__ snorm, const float* __restrict__ dinv,
    const float* __restrict__ bias, const float* __restrict__ t,
    float* __restrict__ h, int n)
{
    int node = blockIdx.x * 8 + (threadIdx.x >> 5);
    if (node >= n) return;
    const int lane = threadIdx.x & 31;
    const int f4 = lane * 4;

    float d = __ldg(dinv + node);
    float d2 = d * d;
    float4 tv = *reinterpret_cast<const float4*>(t + (size_t)node * FDIM + f4);
    float4 bv = *reinterpret_cast<const float4*>(bias + f4);
    float4 acc;
    acc.x = fmaf(tv.x, d2, bv.x);
    acc.y = fmaf(tv.y, d2, bv.y);
    acc.z = fmaf(tv.z, d2, bv.z);
    acc.w = fmaf(tv.w, d2, bv.w);

    int j = __ldg(rowptr + node);
    const int jend = __ldg(rowptr + node + 1);

    for (; j + 1 < jend; j += 2) {
        int r0 = __ldg(srow + j);
        int r1 = __ldg(srow + j + 1);
        float w0 = __ldg(snorm + j);
        float w1 = __ldg(snorm + j + 1);
        float4 v0 = *reinterpret_cast<const float4*>(t + (size_t)r0 * FDIM + f4);
        float4 v1 = *reinterpret_cast<const float4*>(t + (size_t)r1 * FDIM + f4);
        acc.x = fmaf(v0.x, w0, acc.x); acc.y = fmaf(v0.y, w0, acc.y);
        acc.z = fmaf(v0.z, w0, acc.z); acc.w = fmaf(v0.w, w0, acc.w);
        acc.x = fmaf(v1.x, w1, acc.x); acc.y = fmaf(v1.y, w1, acc.y);
        acc.z = fmaf(v1.z, w1, acc.z); acc.w = fmaf(v1.w, w1, acc.w);
    }
    if (j < jend) {
        int r0 = __ldg(srow + j);
        float w0 = __ldg(snorm + j);
        float4 v0 = *reinterpret_cast<const float4*>(t + (size_t)r0 * FDIM + f4);
        acc.x = fmaf(v0.x, w0, acc.x); acc.y = fmaf(v0.y, w0, acc.y);
        acc.z = fmaf(v0.z, w0, acc.z); acc.w = fmaf(v0.w, w0, acc.w);
    }

    *reinterpret_cast<float4*>(h + (size_t)node * FDIM + f4) = acc;
}

// ---------------- launch ----------------

extern "C" void kernel_launch(void* const* d_in, const int* in_sizes, int n_in,
                              void* d_out, int out_size) {
    const float* x    = (const float*)d_in[0];
    const int*   ei   = (const int*)  d_in[1];
    const float* ew   = (const float*)d_in[2];
    const float* Wc[4] = {(const float*)d_in[3], (const float*)d_in[5],
                          (const float*)d_in[7], (const float*)d_in[9]};
    const float* bc[4] = {(const float*)d_in[4], (const float*)d_in[6],
                          (const float*)d_in[8], (const float*)d_in[10]};
    const float* Wout = (const float*)d_in[11];
    const float* bout = (const float*)d_in[12];
    float* out = (float*)d_out;

    const int N = in_sizes[0] / FDIM;
    const int E = in_sizes[2];
    const int* rowp = ei;
    const int* colp = ei + E;

    float *t, *h, *deg, *dinv, *snorm;
    int *cnt, *rowptr, *cur, *srow, *bsum, *boffs;
    __nv_bfloat16 *whi, *wlo;
    cudaGetSymbolAddress((void**)&t, g_t);
    cudaGetSymbolAddress((void**)&h, g_h);
    cudaGetSymbolAddress((void**)&deg, g_deg);
    cudaGetSymbolAddress((void**)&dinv, g_dinv);
    cudaGetSymbolAddress((void**)&cnt, g_cnt);
    cudaGetSymbolAddress((void**)&rowptr, g_rowptr);
    cudaGetSymbolAddress((void**)&cur, g_cursor);
    cudaGetSymbolAddress((void**)&srow, g_srow);
    cudaGetSymbolAddress((void**)&snorm, g_snorm);
    cudaGetSymbolAddress((void**)&bsum, g_bsum);
    cudaGetSymbolAddress((void**)&boffs, g_boffs);
    cudaGetSymbolAddress((void**)&whi, g_whi);
    cudaGetSymbolAddress((void**)&wlo, g_wlo);

    static const int SMEM_DYN = 98304;
    cudaFuncSetAttribute(k_gemm_mma, cudaFuncAttributeMaxDynamicSharedMemorySize, SMEM_DYN);

    const int TB = 256;
    const int nScanBlk = (N + SCAN_B - 1) / SCAN_B;
    const int wpBlocks = (16384 + TB - 1) / TB;
    const int gemmBlocks = (N + BM - 1) / BM;
    const int aggBlocks  = (N + 7) / 8;

    // Launch order arranged so k_gemm_mma is the 6th launch (ncu -s 5 -c 1).
    k_init<<<(N + TB - 1) / TB, TB>>>(deg, cnt, cur, N);                       // 1
    k_deg_hist<<<(E + TB - 1) / TB, TB>>>(colp, ew, deg, cnt, E);              // 2
    k_dinv<<<(N + TB - 1) / TB, TB>>>(deg, dinv, N);                           // 3
    k_wprep<<<wpBlocks, TB>>>(Wc[0], whi, wlo);                                // 4
    k_scan_local<<<nScanBlk, SCAN_B>>>(cnt, rowptr, bsum, N);                  // 5
    k_gemm_mma<<<gemmBlocks, TB, SMEM_DYN>>>(x, whi, wlo, nullptr, t, N, 0, 0);// 6 <- profiled
    k_scan_mid<<<1, MAXBLK>>>(bsum, boffs, nScanBlk);                          // 7
    k_scan_add<<<nScanBlk, SCAN_B>>>(rowptr, boffs, N, E);                     // 8
    k_fill<<<(E + TB - 1) / TB, TB>>>(rowp, colp, ew, dinv, rowptr, cur, srow, snorm, E);
    for (int l = 1; l < 4; l++)
        k_wprep<<<wpBlocks, TB>>>(Wc[l], whi + l * 16384, wlo + l * 16384);
    k_wprep<<<wpBlocks, TB>>>(Wout, whi + 4 * 16384, wlo + 4 * 16384);

    k_aggregate<<<aggBlocks, TB>>>(rowptr, srow, snorm, dinv, bc[0], t, h, N);

    for (int l = 1; l < 4; l++) {
        k_gemm_mma<<<gemmBlocks, TB, SMEM_DYN>>>(h, whi + l * 16384, wlo + l * 16384,
                                                 nullptr, t, N, 1, 0);
        k_aggregate<<<aggBlocks, TB>>>(rowptr, srow, snorm, dinv, bc[l], t, h, N);
    }

    k_gemm_mma<<<gemmBlocks, TB, SMEM_DYN>>>(h, whi + 4 * 16384, wlo + 4 * 16384,
                                             bout, out, N, 0, 1);
}

// round 7
// speedup vs baseline: 2.2006x; 1.0187x over previous
#include <cuda_runtime.h>
#include <cuda_bf16.h>
#include <cstdint>

// ---------------------------------------------------------------------------
// GCN: 4x GCNConv(128->128) + output linear(128->128), N=100000, E=1600000.
// Round 7: GEMM as launch #4 (ncu lands there), software-pipelined mainloop,
// aggregate unrolled x4.
// ---------------------------------------------------------------------------

#define NMAX 100096
#define EMAX 1600000
#define FDIM 128
#define SCAN_B 1024
#define MAXBLK 128
#define BM 64

__device__ float g_t[(size_t)NMAX * FDIM];
__device__ float g_h[(size_t)NMAX * FDIM];
__device__ float g_deg[NMAX];
__device__ float g_dinv[NMAX];
__device__ int   g_cnt[NMAX];
__device__ int   g_rowptr[NMAX + 1];
__device__ int   g_cursor[NMAX];
__device__ int   g_srow[EMAX];
__device__ float g_snorm[EMAX];
__device__ int   g_bsum[MAXBLK];
__device__ int   g_boffs[MAXBLK];
__device__ __align__(16) __nv_bfloat16 g_whi[5 * 16384];
__device__ __align__(16) __nv_bfloat16 g_wlo[5 * 16384];

// ---------------- helpers ----------------

__device__ __forceinline__ uint32_t smem_u32(const void* p) {
    uint32_t a;
    asm("{ .reg .u64 t; cvta.to.shared.u64 t, %1; cvt.u32.u64 %0, t; }" : "=r"(a) : "l"(p));
    return a;
}

__device__ __forceinline__ void ldsm4(uint32_t& r0, uint32_t& r1, uint32_t& r2,
                                      uint32_t& r3, uint32_t addr) {
    asm volatile("ldmatrix.sync.aligned.m8n8.x4.shared.b16 {%0,%1,%2,%3}, [%4];"
                 : "=r"(r0), "=r"(r1), "=r"(r2), "=r"(r3) : "r"(addr));
}

__device__ __forceinline__ void mma16816(float* c, const uint32_t* a,
                                         uint32_t b0, uint32_t b1) {
    asm volatile(
        "mma.sync.aligned.m16n8k16.row.col.f32.bf16.bf16.f32 "
        "{%0,%1,%2,%3}, {%4,%5,%6,%7}, {%8,%9}, {%0,%1,%2,%3};"
        : "+f"(c[0]), "+f"(c[1]), "+f"(c[2]), "+f"(c[3])
        : "r"(a[0]), "r"(a[1]), "r"(a[2]), "r"(a[3]), "r"(b0), "r"(b1));
}

__device__ __forceinline__ void cp16(uint32_t dst, const void* src) {
    asm volatile("cp.async.ca.shared.global [%0], [%1], 16;" :: "r"(dst), "l"(src));
}

// XOR-swizzled: 256B rows (128 bf16); addr(r,k) = r*256 + ((k>>3)^(r&7))*16 + (k&7)*2
__device__ __forceinline__ uint32_t swz(int r, int k) {
    return (uint32_t)((r << 8) + ((((k >> 3) ^ (r & 7)) << 4)) + ((k & 7) << 1));
}

// ---------------- degree + histogram ----------------

__global__ void k_init(float* __restrict__ deg, int* __restrict__ cnt,
                       int* __restrict__ cur, int n) {
    int i = blockIdx.x * blockDim.x + threadIdx.x;
    if (i < n) { deg[i] = 1.0f; cnt[i] = 0; cur[i] = 0; }
}

__global__ void k_deg_hist(const int* __restrict__ col, const float* __restrict__ ew,
                           float* __restrict__ deg, int* __restrict__ cnt, int E) {
    int e = blockIdx.x * blockDim.x + threadIdx.x;
    if (e < E) {
        int c = col[e];
        atomicAdd(&deg[c], ew[e]);
        atomicAdd(&cnt[c], 1);
    }
}

__global__ void k_dinv(const float* __restrict__ deg, float* __restrict__ dinv, int n) {
    int i = blockIdx.x * blockDim.x + threadIdx.x;
    if (i < n) {
        float d = deg[i];
        dinv[i] = (d > 0.0f) ? rsqrtf(d) : 0.0f;
    }
}

// ---------------- 3-phase scan ----------------

__global__ void __launch_bounds__(SCAN_B) k_scan_local(
    const int* __restrict__ cnt, int* __restrict__ rowptr,
    int* __restrict__ bsum, int n)
{
    __shared__ int s[SCAN_B];
    const int tid = threadIdx.x;
    const int i = blockIdx.x * SCAN_B + tid;
    int v = (i < n) ? cnt[i] : 0;
    s[tid] = v;
    __syncthreads();
#pragma unroll
    for (int ofs = 1; ofs < SCAN_B; ofs <<= 1) {
        int t = (tid >= ofs) ? s[tid - ofs] : 0;
        __syncthreads();
        s[tid] += t;
        __syncthreads();
    }
    if (i < n) rowptr[i] = s[tid] - v;
    if (tid == SCAN_B - 1) bsum[blockIdx.x] = s[tid];
}

__global__ void __launch_bounds__(MAXBLK) k_scan_mid(
    const int* __restrict__ bsum, int* __restrict__ boffs, int nb)
{
    __shared__ int s[MAXBLK];
    const int tid = threadIdx.x;
    int v = (tid < nb) ? bsum[tid] : 0;
    s[tid] = v;
    __syncthreads();
#pragma unroll
    for (int ofs = 1; ofs < MAXBLK; ofs <<= 1) {
        int t = (tid >= ofs) ? s[tid - ofs] : 0;
        __syncthreads();
        s[tid] += t;
        __syncthreads();
    }
    if (tid < nb) boffs[tid] = s[tid] - v;
}

__global__ void __launch_bounds__(SCAN_B) k_scan_add(
    int* __restrict__ rowptr, const int* __restrict__ boffs, int n, int E)
{
    const int i = blockIdx.x * SCAN_B + threadIdx.x;
    if (i < n) rowptr[i] += boffs[blockIdx.x];
    if (i == 0) rowptr[n] = E;
}

// ---------------- counting-sort fill ----------------

__global__ void k_fill(const int* __restrict__ row, const int* __restrict__ col,
                       const float* __restrict__ ew, const float* __restrict__ dinv,
                       const int* __restrict__ rowptr, int* __restrict__ cur,
                       int* __restrict__ srow, float* __restrict__ snorm, int E) {
    int e = blockIdx.x * blockDim.x + threadIdx.x;
    if (e >= E) return;
    int r = row[e];
    int c = col[e];
    int pos = rowptr[c] + atomicAdd(&cur[c], 1);
    srow[pos] = r;
    snorm[pos] = dinv[r] * ew[e] * dinv[c];
}

// ---------------- weight prep ----------------

__global__ void k_wprep(const float* __restrict__ W, __nv_bfloat16* __restrict__ dhi,
                        __nv_bfloat16* __restrict__ dlo) {
    int idx = blockIdx.x * blockDim.x + threadIdx.x;
    if (idx >= 16384) return;
    int n = idx >> 7, k = idx & 127;
    float w = W[k * 128 + n];                 // B[n][k] = W[k][n]
    __nv_bfloat16 hi = __float2bfloat16(w);
    __nv_bfloat16 lo = __float2bfloat16(w - __bfloat162float(hi));
    dhi[n * 128 + k] = hi;
    dlo[n * 128 + k] = lo;
}

// ---------------- HMMA GEMM: C[M,128] = act(A[M,128]) @ W (+bias) ----------------
// BM=64, 8 warps 2x4, XOR swizzle, cp.async W staging, pipelined mainloop.

__global__ void __launch_bounds__(256, 2) k_gemm_mma(
    const float* __restrict__ A, const __nv_bfloat16* __restrict__ whi,
    const __nv_bfloat16* __restrict__ wlo, const float* __restrict__ bias,
    float* __restrict__ C, int M, int doRelu, int doBias)
{
    extern __shared__ char sm[];
    char* sAhi = sm;
    char* sAlo = sm + 16384;
    char* sWhi = sm + 32768;
    char* sWlo = sm + 65536;

    const int tid = threadIdx.x;
    const int wid = tid >> 5;
    const int lane = tid & 31;
    const int rbase = blockIdx.x * BM;

    const uint32_t uWhi = smem_u32(sWhi);
    const uint32_t uWlo = smem_u32(sWlo);
    const uint32_t uAhi = smem_u32(sAhi);
    const uint32_t uAlo = smem_u32(sAlo);

    for (int i = tid; i < 2048; i += 256) {
        int r = i >> 4, c = i & 15;
        uint32_t doff = (uint32_t)((r << 8) + ((c ^ (r & 7)) << 4));
        cp16(uWhi + doff, whi + r * 128 + c * 8);
        cp16(uWlo + doff, wlo + r * 128 + c * 8);
    }
    asm volatile("cp.async.commit_group;" ::: "memory");

    for (int idx = tid; idx < BM * 32; idx += 256) {
        int row = idx >> 5;
        int c4 = (idx & 31) << 2;
        int grow = rbase + row;
        float4 av = make_float4(0.f, 0.f, 0.f, 0.f);
        if (grow < M)
            av = *reinterpret_cast<const float4*>(A + (size_t)grow * FDIM + c4);
        if (doRelu) {
            av.x = fmaxf(av.x, 0.f); av.y = fmaxf(av.y, 0.f);
            av.z = fmaxf(av.z, 0.f); av.w = fmaxf(av.w, 0.f);
        }
        __nv_bfloat162 h01, h23, l01, l23;
        h01.x = __float2bfloat16(av.x);
        h01.y = __float2bfloat16(av.y);
        h23.x = __float2bfloat16(av.z);
        h23.y = __float2bfloat16(av.w);
        l01.x = __float2bfloat16(av.x - __bfloat162float(h01.x));
        l01.y = __float2bfloat16(av.y - __bfloat162float(h01.y));
        l23.x = __float2bfloat16(av.z - __bfloat162float(h23.x));
        l23.y = __float2bfloat16(av.w - __bfloat162float(h23.y));
        uint32_t off = swz(row, c4);
        *reinterpret_cast<uint32_t*>(sAhi + off)     = *reinterpret_cast<uint32_t*>(&h01);
        *reinterpret_cast<uint32_t*>(sAhi + off + 4) = *reinterpret_cast<uint32_t*>(&h23);
        *reinterpret_cast<uint32_t*>(sAlo + off)     = *reinterpret_cast<uint32_t*>(&l01);
        *reinterpret_cast<uint32_t*>(sAlo + off + 4) = *reinterpret_cast<uint32_t*>(&l23);
    }
    asm volatile("cp.async.wait_group 0;" ::: "memory");
    __syncthreads();

    const int warpRow = (wid & 1) * 32;
    const int warpCol = (wid >> 1) * 32;
    const int a_r = lane & 15;
    const int a_k = (lane >> 4) << 3;
    const int b_n = (lane & 7) + ((lane >> 4) << 3);
    const int b_k = ((lane >> 3) & 1) << 3;

    const uint32_t aTerm[3] = {uAhi, uAlo, uAhi};
    const uint32_t bTerm[3] = {uWhi, uWhi, uWlo};

    float c[2][4][4];
#pragma unroll
    for (int mi = 0; mi < 2; mi++)
#pragma unroll
        for (int ni = 0; ni < 4; ni++)
#pragma unroll
            for (int q = 0; q < 4; q++) c[mi][ni][q] = 0.0f;

    // software-pipelined over 24 (term, k-step) iterations
    uint32_t a0[2][4], a1[2][4], b0[2][4], b1[2][4];
    {
        const uint32_t ab = aTerm[0], bb = bTerm[0];
        ldsm4(a0[0][0], a0[0][1], a0[0][2], a0[0][3], ab + swz(warpRow + a_r,      a_k));
        ldsm4(a1[0][0], a1[0][1], a1[0][2], a1[0][3], ab + swz(warpRow + 16 + a_r, a_k));
        ldsm4(b0[0][0], b0[0][1], b0[0][2], b0[0][3], bb + swz(warpCol + b_n,      b_k));
        ldsm4(b1[0][0], b1[0][1], b1[0][2], b1[0][3], bb + swz(warpCol + 16 + b_n, b_k));
    }
#pragma unroll
    for (int it = 0; it < 24; it++) {
        const int cur = it & 1, nxt = cur ^ 1;
        if (it < 23) {
            const int itn = it + 1;
            const uint32_t ab = aTerm[itn >> 3], bb = bTerm[itn >> 3];
            const int k0 = (itn & 7) << 4;
            ldsm4(a0[nxt][0], a0[nxt][1], a0[nxt][2], a0[nxt][3],
                  ab + swz(warpRow + a_r,      k0 + a_k));
            ldsm4(a1[nxt][0], a1[nxt][1], a1[nxt][2], a1[nxt][3],
                  ab + swz(warpRow + 16 + a_r, k0 + a_k));
            ldsm4(b0[nxt][0], b0[nxt][1], b0[nxt][2], b0[nxt][3],
                  bb + swz(warpCol + b_n,      k0 + b_k));
            ldsm4(b1[nxt][0], b1[nxt][1], b1[nxt][2], b1[nxt][3],
                  bb + swz(warpCol + 16 + b_n, k0 + b_k));
        }
        mma16816(c[0][0], a0[cur], b0[cur][0], b0[cur][1]);
        mma16816(c[0][1], a0[cur], b0[cur][2], b0[cur][3]);
        mma16816(c[0][2], a0[cur], b1[cur][0], b1[cur][1]);
        mma16816(c[0][3], a0[cur], b1[cur][2], b1[cur][3]);
        mma16816(c[1][0], a1[cur], b0[cur][0], b0[cur][1]);
        mma16816(c[1][1], a1[cur], b0[cur][2], b0[cur][3]);
        mma16816(c[1][2], a1[cur], b1[cur][0], b1[cur][1]);
        mma16816(c[1][3], a1[cur], b1[cur][2], b1[cur][3]);
    }

    const int crow = lane >> 2;
    const int ccol = (lane & 3) * 2;
#pragma unroll
    for (int mi = 0; mi < 2; mi++) {
#pragma unroll
        for (int ni = 0; ni < 4; ni++) {
            int colg = warpCol + ni * 8 + ccol;
            float bx = 0.f, by = 0.f;
            if (doBias) { bx = bias[colg]; by = bias[colg + 1]; }
            int r0 = rbase + warpRow + mi * 16 + crow;
            int r1 = r0 + 8;
            if (r0 < M) {
                float2 v = make_float2(c[mi][ni][0] + bx, c[mi][ni][1] + by);
                *reinterpret_cast<float2*>(C + (size_t)r0 * FDIM + colg) = v;
            }
            if (r1 < M) {
                float2 v = make_float2(c[mi][ni][2] + bx, c[mi][ni][3] + by);
                *reinterpret_cast<float2*>(C + (size_t)r1 * FDIM + colg) = v;
            }
        }
    }
}

// ---------------- CSR aggregate: one warp per node, unrolled x4 ----------------

__global__ void __launch_bounds__(256) k_aggregate(
    const int* __restrict__ rowptr, const int* __restrict__ srow,
    const float* __restrict__ snorm, const float* __restrict__ dinv,
    const float* __restrict__ bias, const float* __restrict__ t,
    float* __restrict__ h, int n)
{
    int node = blockIdx.x * 8 + (threadIdx.x >> 5);
    if (node >= n) return;
    const int lane = threadIdx.x & 31;
    const int f4 = lane * 4;

    float d = __ldg(dinv + node);
    float d2 = d * d;
    float4 tv = *reinterpret_cast<const float4*>(t + (size_t)node * FDIM + f4);
    float4 bv = *reinterpret_cast<const float4*>(bias + f4);
    float4 acc;
    acc.x = fmaf(tv.x, d2, bv.x);
    acc.y = fmaf(tv.y, d2, bv.y);
    acc.z = fmaf(tv.z, d2, bv.z);
    acc.w = fmaf(tv.w, d2, bv.w);

    int j = __ldg(rowptr + node);
    const int jend = __ldg(rowptr + node + 1);

    for (; j + 3 < jend; j += 4) {
        int r0 = __ldg(srow + j);
        int r1 = __ldg(srow + j + 1);
        int r2 = __ldg(srow + j + 2);
        int r3 = __ldg(srow + j + 3);
        float w0 = __ldg(snorm + j);
        float w1 = __ldg(snorm + j + 1);
        float w2 = __ldg(snorm + j + 2);
        float w3 = __ldg(snorm + j + 3);
        float4 v0 = *reinterpret_cast<const float4*>(t + (size_t)r0 * FDIM + f4);
        float4 v1 = *reinterpret_cast<const float4*>(t + (size_t)r1 * FDIM + f4);
        float4 v2 = *reinterpret_cast<const float4*>(t + (size_t)r2 * FDIM + f4);
        float4 v3 = *reinterpret_cast<const float4*>(t + (size_t)r3 * FDIM + f4);
        acc.x = fmaf(v0.x, w0, acc.x); acc.y = fmaf(v0.y, w0, acc.y);
        acc.z = fmaf(v0.z, w0, acc.z); acc.w = fmaf(v0.w, w0, acc.w);
        acc.x = fmaf(v1.x, w1, acc.x); acc.y = fmaf(v1.y, w1, acc.y);
        acc.z = fmaf(v1.z, w1, acc.z); acc.w = fmaf(v1.w, w1, acc.w);
        acc.x = fmaf(v2.x, w2, acc.x); acc.y = fmaf(v2.y, w2, acc.y);
        acc.z = fmaf(v2.z, w2, acc.z); acc.w = fmaf(v2.w, w2, acc.w);
        acc.x = fmaf(v3.x, w3, acc.x); acc.y = fmaf(v3.y, w3, acc.y);
        acc.z = fmaf(v3.z, w3, acc.z); acc.w = fmaf(v3.w, w3, acc.w);
    }
    for (; j < jend; j++) {
        int r0 = __ldg(srow + j);
        float w0 = __ldg(snorm + j);
        float4 v0 = *reinterpret_cast<const float4*>(t + (size_t)r0 * FDIM + f4);
        acc.x = fmaf(v0.x, w0, acc.x); acc.y = fmaf(v0.y, w0, acc.y);
        acc.z = fmaf(v0.z, w0, acc.z); acc.w = fmaf(v0.w, w0, acc.w);
    }

    *reinterpret_cast<float4*>(h + (size_t)node * FDIM + f4) = acc;
}

// ---------------- launch ----------------

extern "C" void kernel_launch(void* const* d_in, const int* in_sizes, int n_in,
                              void* d_out, int out_size) {
    const float* x    = (const float*)d_in[0];
    const int*   ei   = (const int*)  d_in[1];
    const float* ew   = (const float*)d_in[2];
    const float* Wc[4] = {(const float*)d_in[3], (const float*)d_in[5],
                          (const float*)d_in[7], (const float*)d_in[9]};
    const float* bc[4] = {(const float*)d_in[4], (const float*)d_in[6],
                          (const float*)d_in[8], (const float*)d_in[10]};
    const float* Wout = (const float*)d_in[11];
    const float* bout = (const float*)d_in[12];
    float* out = (float*)d_out;

    const int N = in_sizes[0] / FDIM;
    const int E = in_sizes[2];
    const int* rowp = ei;
    const int* colp = ei + E;

    float *t, *h, *deg, *dinv, *snorm;
    int *cnt, *rowptr, *cur, *srow, *bsum, *boffs;
    __nv_bfloat16 *whi, *wlo;
    cudaGetSymbolAddress((void**)&t, g_t);
    cudaGetSymbolAddress((void**)&h, g_h);
    cudaGetSymbolAddress((void**)&deg, g_deg);
    cudaGetSymbolAddress((void**)&dinv, g_dinv);
    cudaGetSymbolAddress((void**)&cnt, g_cnt);
    cudaGetSymbolAddress((void**)&rowptr, g_rowptr);
    cudaGetSymbolAddress((void**)&cur, g_cursor);
    cudaGetSymbolAddress((void**)&srow, g_srow);
    cudaGetSymbolAddress((void**)&snorm, g_snorm);
    cudaGetSymbolAddress((void**)&bsum, g_bsum);
    cudaGetSymbolAddress((void**)&boffs, g_boffs);
    cudaGetSymbolAddress((void**)&whi, g_whi);
    cudaGetSymbolAddress((void**)&wlo, g_wlo);

    static const int SMEM_DYN = 98304;
    cudaFuncSetAttribute(k_gemm_mma, cudaFuncAttributeMaxDynamicSharedMemorySize, SMEM_DYN);

    const int TB = 256;
    const int nScanBlk = (N + SCAN_B - 1) / SCAN_B;
    const int wpBlocks = (16384 + TB - 1) / TB;
    const int gemmBlocks = (N + BM - 1) / BM;
    const int aggBlocks  = (N + 7) / 8;

    // Launch order: k_gemm_mma is launch #4 (ncu has captured my 4th launch
    // in every round so far).
    k_wprep<<<wpBlocks, TB>>>(Wc[0], whi, wlo);                                // 1
    k_init<<<(N + TB - 1) / TB, TB>>>(deg, cnt, cur, N);                       // 2
    k_deg_hist<<<(E + TB - 1) / TB, TB>>>(colp, ew, deg, cnt, E);              // 3
    k_gemm_mma<<<gemmBlocks, TB, SMEM_DYN>>>(x, whi, wlo, nullptr, t, N, 0, 0);// 4 <- profiled
    k_dinv<<<(N + TB - 1) / TB, TB>>>(deg, dinv, N);                           // 5
    k_scan_local<<<nScanBlk, SCAN_B>>>(cnt, rowptr, bsum, N);                  // 6
    k_scan_mid<<<1, MAXBLK>>>(bsum, boffs, nScanBlk);                          // 7
    k_scan_add<<<nScanBlk, SCAN_B>>>(rowptr, boffs, N, E);                     // 8
    k_fill<<<(E + TB - 1) / TB, TB>>>(rowp, colp, ew, dinv, rowptr, cur, srow, snorm, E);
    for (int l = 1; l < 4; l++)
        k_wprep<<<wpBlocks, TB>>>(Wc[l], whi + l * 16384, wlo + l * 16384);
    k_wprep<<<wpBlocks, TB>>>(Wout, whi + 4 * 16384, wlo + 4 * 16384);

    k_aggregate<<<aggBlocks, TB>>>(rowptr, srow, snorm, dinv, bc[0], t, h, N);

    for (int l = 1; l < 4; l++) {
        k_gemm_mma<<<gemmBlocks, TB, SMEM_DYN>>>(h, whi + l * 16384, wlo + l * 16384,
                                                 nullptr, t, N, 1, 0);
        k_aggregate<<<aggBlocks, TB>>>(rowptr, srow, snorm, dinv, bc[l], t, h, N);
    }

    k_gemm_mma<<<gemmBlocks, TB, SMEM_DYN>>>(h, whi + 4 * 16384, wlo + 4 * 16384,
                                             bout, out, N, 0, 1);
}